// round 2
// baseline (speedup 1.0000x reference)
#include <cuda_runtime.h>
#include <cuda_bf16.h>

// ---------------------------------------------------------------------------
// Conv2d_STN: B=8, C=128, H=W=56, k=3, Ho=Wo=54, N=B*Ho*Wo=23328, O=256
//
// Pipeline:
//   K0: transpose lin_w (256x1152) -> g_linwT (1152x256)   [coalesced gemm reads]
//   K1: conv1 3x3 pad1 (128->128) + bias + relu -> g_h
//   K2: conv2 3x3 valid (128->6) -> theta; writes out / (ident-theta) / auxx / auxy
//   K3: bilinear 3x3 patch gather (128 ch) + GEMM Nx1152 @ 1152x256 -> score
//
// Output layout (concatenated tuple, floats):
//   score  [8,256,54,54]  @ 0        (5,971,968)
//   diff   [N,2,3]        @ 5971968  (139,968)
//   out    [8,6,54,54]    @ 6111936  (139,968)
//   auxx   [N,3,3]        @ 6251904  (209,952)
//   auxy   [N,3,3]        @ 6461856  (209,952)
// ---------------------------------------------------------------------------

#define Bsz   8
#define Cch   128
#define Hh    56
#define Ww    56
#define HW    3136            // 56*56
#define CHW   401408          // 128*3136
#define Ho    54
#define NHW   2916            // 54*54
#define Ntot  23328           // 8*2916
#define Oo    256
#define Kdim  1152            // 128*9

#define SCORE_OFF 0
#define DIFF_OFF  5971968
#define OUT_OFF   6111936
#define AUXX_OFF  6251904
#define AUXY_OFF  6461856

__device__ float g_h[Bsz * Cch * Hh * Ww];     // 12.8 MB intermediate (conv1 out)
__device__ float g_linwT[Kdim * Oo];           // 1.18 MB transposed linear weight

// ---------------- K0: transpose lin_w --------------------------------------
__global__ void k_transpose(const float* __restrict__ lin_w) {
    int e = blockIdx.x * 256 + threadIdx.x;
    if (e < Oo * Kdim) {
        int o = e / Kdim, k = e % Kdim;
        g_linwT[k * Oo + o] = lin_w[e];
    }
}

// ---------------- K1: conv1 + bias + relu ----------------------------------
// block: (ho, cog, b); 256 threads. Thread: co_l = tid&31, wo group = tid>>5 (7 wo each).
__global__ __launch_bounds__(256) void k_conv1(const float* __restrict__ x,
                                               const float* __restrict__ w,
                                               const float* __restrict__ bias) {
    __shared__ float s_in[3][16][58];     // [kh][ci][col], col = wo+ (-1..56) zero padded
    __shared__ float s_w[16][9][32];      // [ci][kh*3+kw][co_l]

    const int ho  = blockIdx.x;
    const int cog = blockIdx.y;
    const int b   = blockIdx.z;
    const int tid = threadIdx.x;
    const int co_l = tid & 31;
    const int wo0  = (tid >> 5) * 7;

    float acc[7] = {0.f, 0.f, 0.f, 0.f, 0.f, 0.f, 0.f};

    for (int ci0 = 0; ci0 < Cch; ci0 += 16) {
        // load input rows (3 x 16ci x 58) with zero padding
        for (int e = tid; e < 3 * 16 * 58; e += 256) {
            int kh  = e / (16 * 58);
            int r   = e % (16 * 58);
            int ci  = r / 58;
            int col = r % 58;
            int y   = ho - 1 + kh;
            int xc  = col - 1;
            float v = 0.f;
            if ((unsigned)y < 56u && (unsigned)xc < 56u)
                v = x[((b * Cch + ci0 + ci) * Hh + y) * Ww + xc];
            s_in[kh][ci][col] = v;
        }
        // load weights (16ci x 9 x 32co)
        for (int e = tid; e < 16 * 9 * 32; e += 256) {
            int ci = e / 288;
            int r  = e % 288;
            int t  = r / 32;
            int co = r & 31;
            s_w[ci][t][co] = w[(cog * 32 + co) * Kdim + (ci0 + ci) * 9 + t];
        }
        __syncthreads();

        #pragma unroll 4
        for (int ci = 0; ci < 16; ci++) {
            float wr[9];
            #pragma unroll
            for (int t = 0; t < 9; t++) wr[t] = s_w[ci][t][co_l];
            #pragma unroll
            for (int kh = 0; kh < 3; kh++) {
                float xv[9];
                #pragma unroll
                for (int u = 0; u < 9; u++) xv[u] = s_in[kh][ci][wo0 + u];
                #pragma unroll
                for (int kw = 0; kw < 3; kw++) {
                    float wv = wr[kh * 3 + kw];
                    #pragma unroll
                    for (int u = 0; u < 7; u++)
                        acc[u] = fmaf(xv[u + kw], wv, acc[u]);
                }
            }
        }
        __syncthreads();
    }

    // epilogue: bias + relu, stage to smem for coalesced store
    const int co = cog * 32 + co_l;
    const float bv = bias[co];
    float* s_out = &s_w[0][0][0];   // reuse (needs 1792 floats)
    #pragma unroll
    for (int u = 0; u < 7; u++)
        s_out[co_l * 56 + wo0 + u] = fmaxf(acc[u] + bv, 0.f);
    __syncthreads();
    for (int e = tid; e < 32 * 56; e += 256) {
        int col = e / 56, wo = e % 56;
        g_h[((b * Cch + cog * 32 + col) * Hh + ho) * Ww + wo] = s_out[e];
    }
}

// ---------------- K2: conv2 (valid) -> theta / out / diff / auxx / auxy ----
__global__ __launch_bounds__(256) void k_conv2(const float* __restrict__ w1,
                                               const int* __restrict__ check,
                                               float* __restrict__ out) {
    __shared__ float s_w[128][9][6];   // [c][t][ch]
    for (int e = threadIdx.x; e < 128 * 54; e += 256) {
        int c = e / 54, r = e % 54, t = r / 6, ch = r % 6;
        s_w[c][t][ch] = w1[ch * Kdim + c * 9 + t];
    }
    __syncthreads();

    int n = blockIdx.x * 256 + threadIdx.x;
    if (n >= Ntot) return;
    int b = n / NHW, r = n % NHW, wo = r / Ho, ho = r % Ho;

    float acc[6] = {0.f, 0.f, 0.f, 0.f, 0.f, 0.f};
    const float* hb = g_h + b * CHW;
    for (int c = 0; c < Cch; c++) {
        const float* hc = hb + c * HW;
        #pragma unroll
        for (int i = 0; i < 3; i++) {
            #pragma unroll
            for (int j = 0; j < 3; j++) {
                float hv = hc[(ho + i) * Ww + wo + j];
                #pragma unroll
                for (int ch = 0; ch < 6; ch++)
                    acc[ch] = fmaf(hv, s_w[c][i * 3 + j][ch], acc[ch]);
            }
        }
    }

    const float scale = 1.0f - (float)check[0];
    const float ident6[6] = {1.f, 0.f, 0.f, 0.f, 1.f, 0.f};
    float th[6];
    #pragma unroll
    for (int ch = 0; ch < 6; ch++) {
        float cv = acc[ch] * scale;
        th[ch] = cv + ident6[ch];
        out[OUT_OFF  + ((b * 6 + ch) * Ho + ho) * Ho + wo] = th[ch];
        out[DIFF_OFF + n * 6 + ch] = -cv;   // ident23 - theta
    }

    #pragma unroll
    for (int i = 0; i < 3; i++) {
        float bi = (2.f * (float)i + 1.f) / 3.f - 1.f;
        #pragma unroll
        for (int j = 0; j < 3; j++) {
            float bj = (2.f * (float)j + 1.f) / 3.f - 1.f;
            float gx = th[0] * bj + th[1] * bi + th[2];
            float gy = th[3] * bj + th[4] * bi + th[5];
            out[AUXX_OFF + n * 9 + i * 3 + j] =
                (gx + 1.0f + (float)wo) * (2.0f / 55.0f) - 1.0f;
            out[AUXY_OFF + n * 9 + i * 3 + j] =
                (gy + 1.0f + (float)ho) * (2.0f / 55.0f) - 1.0f;
        }
    }
}

// ---------------- K3: gather patches + GEMM --------------------------------
// block = 8 consecutive n; 256 threads. Patch layout [nn][c*9+t] in smem.
__global__ __launch_bounds__(256) void k_sample(const float* __restrict__ x,
                                                const float* __restrict__ lin_b,
                                                float* __restrict__ out) {
    __shared__ float s_patch[8][Kdim];          // 36.9 KB
    __shared__ int   s_xi[72], s_yi[72];
    __shared__ float s_wx[72], s_wy[72];
    __shared__ int   s_imgoff[8], s_obase[8];

    const int tid = threadIdx.x;
    const int n0  = blockIdx.x * 8;

    if (tid < 8) {
        int n = n0 + tid;
        int b = n / NHW, r = n % NHW, wo = r / Ho, ho = r % Ho;
        s_imgoff[tid] = b * CHW;
        s_obase[tid]  = b * (Oo * NHW) + ho * Ho + wo;
    }
    if (tid < 72) {
        int nn = tid / 9, t = tid % 9;
        int n = n0 + nn;
        float ax = out[AUXX_OFF + n * 9 + t];
        float ay = out[AUXY_OFF + n * 9 + t];
        float gx = (ax + 1.0f) * 28.0f - 0.5f;   // (aux+1)*W/2 - 0.5
        float gy = (ay + 1.0f) * 28.0f - 0.5f;
        float x0f = floorf(gx), y0f = floorf(gy);
        s_xi[tid] = (int)x0f;  s_yi[tid] = (int)y0f;
        s_wx[tid] = gx - x0f;  s_wy[tid] = gy - y0f;
    }
    __syncthreads();

    // gather: 128 lanes over c, 2 halves over nn
    {
        const int c  = tid & 127;
        const int nh = tid >> 7;
        for (int nn = nh; nn < 8; nn += 2) {
            const float* img = x + s_imgoff[nn] + c * HW;
            #pragma unroll
            for (int t = 0; t < 9; t++) {
                int p  = nn * 9 + t;
                int x0 = s_xi[p], y0 = s_yi[p];
                float wx = s_wx[p], wy = s_wy[p];
                int x0c = min(max(x0, 0), 55),     x1c = min(max(x0 + 1, 0), 55);
                int y0c = min(max(y0, 0), 55),     y1c = min(max(y0 + 1, 0), 55);
                bool vx0 = (unsigned)x0 < 56u,     vx1 = (unsigned)(x0 + 1) < 56u;
                bool vy0 = (unsigned)y0 < 56u,     vy1 = (unsigned)(y0 + 1) < 56u;
                float v00 = (vx0 && vy0) ? img[y0c * Ww + x0c] : 0.f;
                float v01 = (vx1 && vy0) ? img[y0c * Ww + x1c] : 0.f;
                float v10 = (vx0 && vy1) ? img[y1c * Ww + x0c] : 0.f;
                float v11 = (vx1 && vy1) ? img[y1c * Ww + x1c] : 0.f;
                float v = v00 * ((1.f - wx) * (1.f - wy))
                        + v01 * (wx * (1.f - wy))
                        + v10 * ((1.f - wx) * wy)
                        + v11 * (wx * wy);
                s_patch[nn][c * 9 + t] = v;
            }
        }
    }
    __syncthreads();

    // GEMM: thread tid computes output channel o = tid for all 8 n
    const int o = tid;
    float acc[8] = {0.f, 0.f, 0.f, 0.f, 0.f, 0.f, 0.f, 0.f};
    for (int k = 0; k < Kdim; k += 4) {
        float4 pv[8];
        #pragma unroll
        for (int nn = 0; nn < 8; nn++)
            pv[nn] = *(const float4*)&s_patch[nn][k];
        #pragma unroll
        for (int q = 0; q < 4; q++) {
            float wv = g_linwT[(k + q) * Oo + o];
            #pragma unroll
            for (int nn = 0; nn < 8; nn++) {
                float pq = (q == 0) ? pv[nn].x : (q == 1) ? pv[nn].y
                         : (q == 2) ? pv[nn].z : pv[nn].w;
                acc[nn] = fmaf(pq, wv, acc[nn]);
            }
        }
    }
    const float bv = lin_b[o];
    #pragma unroll
    for (int nn = 0; nn < 8; nn++)
        out[SCORE_OFF + s_obase[nn] + o * NHW] = acc[nn] + bv;
}

// ---------------------------------------------------------------------------
extern "C" void kernel_launch(void* const* d_in, const int* in_sizes, int n_in,
                              void* d_out, int out_size) {
    const float* x      = (const float*)d_in[0];
    const float* stn0_w = (const float*)d_in[1];
    const float* stn0_b = (const float*)d_in[2];
    const float* stn1_w = (const float*)d_in[3];
    const float* lin_w  = (const float*)d_in[4];
    const float* lin_b  = (const float*)d_in[5];
    const int*   check  = (const int*)d_in[6];
    float* out = (float*)d_out;

    k_transpose<<<(Oo * Kdim + 255) / 256, 256>>>(lin_w);

    dim3 g1(56, 4, 8);
    k_conv1<<<g1, 256>>>(x, stn0_w, stn0_b);

    k_conv2<<<(Ntot + 255) / 256, 256>>>(stn1_w, check, out);

    k_sample<<<Ntot / 8, 256>>>(x, lin_b, out);
}

// round 3
// speedup vs baseline: 1.0274x; 1.0274x over previous
#include <cuda_runtime.h>
#include <cuda_bf16.h>

// ---------------------------------------------------------------------------
// Conv2d_STN: B=8, C=128, H=W=56, k=3, Ho=Wo=54, N=B*Ho*Wo=23328, O=256
// ---------------------------------------------------------------------------

#define Bsz   8
#define Cch   128
#define Hh    56
#define Ww    56
#define HW    3136
#define CHW   401408
#define Ho    54
#define NHW   2916
#define Ntot  23328
#define Oo    256
#define Kdim  1152

#define SCORE_OFF 0
#define DIFF_OFF  5971968
#define OUT_OFF   6111936
#define AUXX_OFF  6251904
#define AUXY_OFF  6461856

__device__ float g_h[Bsz * Cch * Hh * Ww];     // conv1 output (12.8 MB)
__device__ float g_linwT[Kdim * Oo];           // interleaved: [k][o0*2+{0,1}] = w[o0], w[o0+128]

// ---------------- K0: transpose + interleave lin_w -------------------------
// g_linwT[k*256 + o0*2 + j] = lin_w[(o0 + j*128)*Kdim + k],  o0 in [0,128)
__global__ void k_transpose(const float* __restrict__ lin_w) {
    int e = blockIdx.x * 256 + threadIdx.x;
    if (e < Oo * Kdim) {
        int k = e >> 8;          // e / 256
        int t = e & 255;
        int o0 = t >> 1, j = t & 1;
        g_linwT[e] = lin_w[(o0 + j * 128) * Kdim + k];
    }
}

// ---------------- K1: conv1 + bias + relu ----------------------------------
// block: (ho, cog of 2, b); 256 threads; 64 co per block, 2 co per thread.
__global__ __launch_bounds__(256) void k_conv1(const float* __restrict__ x,
                                               const float* __restrict__ w,
                                               const float* __restrict__ bias) {
    __shared__ float s_in[3][16][58];     // [kh][ci][col], zero-padded cols
    __shared__ float s_w[16][9][64];      // [ci][t][co_local]

    const int ho  = blockIdx.x;
    const int cog = blockIdx.y;           // 0..1 (64 co each)
    const int b   = blockIdx.z;
    const int tid = threadIdx.x;
    const int co_l = tid & 31;
    const int wo0  = (tid >> 5) * 7;

    float acc0[7] = {0,0,0,0,0,0,0};
    float acc1[7] = {0,0,0,0,0,0,0};

    for (int ci0 = 0; ci0 < Cch; ci0 += 16) {
        for (int e = tid; e < 3 * 16 * 58; e += 256) {
            int kh  = e / (16 * 58);
            int r   = e % (16 * 58);
            int ci  = r / 58;
            int col = r % 58;
            int y   = ho - 1 + kh;
            int xc  = col - 1;
            float v = 0.f;
            if ((unsigned)y < 56u && (unsigned)xc < 56u)
                v = x[((b * Cch + ci0 + ci) * Hh + y) * Ww + xc];
            s_in[kh][ci][col] = v;
        }
        for (int e = tid; e < 16 * 9 * 64; e += 256) {
            int ci = e / 576;
            int r  = e % 576;
            int t  = r >> 6;
            int co = r & 63;
            s_w[ci][t][co] = w[(cog * 64 + co) * Kdim + (ci0 + ci) * 9 + t];
        }
        __syncthreads();

        #pragma unroll 2
        for (int ci = 0; ci < 16; ci++) {
            float wr0[9], wr1[9];
            #pragma unroll
            for (int t = 0; t < 9; t++) {
                wr0[t] = s_w[ci][t][co_l];
                wr1[t] = s_w[ci][t][co_l + 32];
            }
            #pragma unroll
            for (int kh = 0; kh < 3; kh++) {
                float xv[9];
                #pragma unroll
                for (int u = 0; u < 9; u++) xv[u] = s_in[kh][ci][wo0 + u];
                #pragma unroll
                for (int kw = 0; kw < 3; kw++) {
                    float w0 = wr0[kh * 3 + kw];
                    float w1 = wr1[kh * 3 + kw];
                    #pragma unroll
                    for (int u = 0; u < 7; u++) {
                        acc0[u] = fmaf(xv[u + kw], w0, acc0[u]);
                        acc1[u] = fmaf(xv[u + kw], w1, acc1[u]);
                    }
                }
            }
        }
        __syncthreads();
    }

    const float bv0 = bias[cog * 64 + co_l];
    const float bv1 = bias[cog * 64 + co_l + 32];
    float* s_out = &s_w[0][0][0];          // 64*56 = 3584 floats, fits
    #pragma unroll
    for (int u = 0; u < 7; u++) {
        s_out[co_l * 56 + wo0 + u]        = fmaxf(acc0[u] + bv0, 0.f);
        s_out[(co_l + 32) * 56 + wo0 + u] = fmaxf(acc1[u] + bv1, 0.f);
    }
    __syncthreads();
    for (int e = tid; e < 64 * 56; e += 256) {
        int col = e / 56, wo = e % 56;
        g_h[((b * Cch + cog * 64 + col) * Hh + ho) * Ww + wo] = s_out[e];
    }
}

// ---------------- K2: conv2 (valid) -> theta / out / diff / auxx / auxy ----
__global__ __launch_bounds__(256) void k_conv2(const float* __restrict__ w1,
                                               const int* __restrict__ check,
                                               float* __restrict__ out) {
    __shared__ float s_w[128][9][6];
    for (int e = threadIdx.x; e < 128 * 54; e += 256) {
        int c = e / 54, r = e % 54, t = r / 6, ch = r % 6;
        s_w[c][t][ch] = w1[ch * Kdim + c * 9 + t];
    }
    __syncthreads();

    int n = blockIdx.x * 256 + threadIdx.x;
    if (n >= Ntot) return;
    int b = n / NHW, r = n % NHW, wo = r / Ho, ho = r % Ho;

    float acc[6] = {0,0,0,0,0,0};
    const float* hb = g_h + b * CHW;
    for (int c = 0; c < Cch; c++) {
        const float* hc = hb + c * HW;
        #pragma unroll
        for (int i = 0; i < 3; i++) {
            #pragma unroll
            for (int j = 0; j < 3; j++) {
                float hv = hc[(ho + i) * Ww + wo + j];
                #pragma unroll
                for (int ch = 0; ch < 6; ch++)
                    acc[ch] = fmaf(hv, s_w[c][i * 3 + j][ch], acc[ch]);
            }
        }
    }

    const float scale = 1.0f - (float)check[0];
    const float ident6[6] = {1.f, 0.f, 0.f, 0.f, 1.f, 0.f};
    float th[6];
    #pragma unroll
    for (int ch = 0; ch < 6; ch++) {
        float cv = acc[ch] * scale;
        th[ch] = cv + ident6[ch];
        out[OUT_OFF  + ((b * 6 + ch) * Ho + ho) * Ho + wo] = th[ch];
        out[DIFF_OFF + n * 6 + ch] = -cv;
    }

    #pragma unroll
    for (int i = 0; i < 3; i++) {
        float bi = (2.f * (float)i + 1.f) / 3.f - 1.f;
        #pragma unroll
        for (int j = 0; j < 3; j++) {
            float bj = (2.f * (float)j + 1.f) / 3.f - 1.f;
            float gx = th[0] * bj + th[1] * bi + th[2];
            float gy = th[3] * bj + th[4] * bi + th[5];
            out[AUXX_OFF + n * 9 + i * 3 + j] =
                (gx + 1.0f + (float)wo) * (2.0f / 55.0f) - 1.0f;
            out[AUXY_OFF + n * 9 + i * 3 + j] =
                (gy + 1.0f + (float)ho) * (2.0f / 55.0f) - 1.0f;
        }
    }
}

// ---------------- K3: gather 16 patches + GEMM (2 o per thread) ------------
__global__ __launch_bounds__(256) void k_sample(const float* __restrict__ x,
                                                const float* __restrict__ lin_b,
                                                float* __restrict__ out) {
    extern __shared__ float s_patch[];          // [16][Kdim] = 73728 B
    __shared__ int   s_xi[144], s_yi[144];
    __shared__ float s_wx[144], s_wy[144];
    __shared__ int   s_imgoff[16], s_obase[16];

    const int tid = threadIdx.x;
    const int n0  = blockIdx.x * 16;

    if (tid < 16) {
        int n = n0 + tid;
        int b = n / NHW, r = n % NHW, wo = r / Ho, ho = r % Ho;
        s_imgoff[tid] = b * CHW;
        s_obase[tid]  = b * (Oo * NHW) + ho * Ho + wo;
    }
    if (tid < 144) {
        int nn = tid / 9, t = tid % 9;
        int n = n0 + nn;
        float ax = out[AUXX_OFF + n * 9 + t];
        float ay = out[AUXY_OFF + n * 9 + t];
        float gx = (ax + 1.0f) * 28.0f - 0.5f;
        float gy = (ay + 1.0f) * 28.0f - 0.5f;
        float x0f = floorf(gx), y0f = floorf(gy);
        s_xi[tid] = (int)x0f;  s_yi[tid] = (int)y0f;
        s_wx[tid] = gx - x0f;  s_wy[tid] = gy - y0f;
    }
    __syncthreads();

    // gather: 128 lanes over c, 2 halves over nn (8 nn each)
    {
        const int c  = tid & 127;
        const int nh = tid >> 7;
        for (int nn = nh; nn < 16; nn += 2) {
            const float* img = x + s_imgoff[nn] + c * HW;
            #pragma unroll
            for (int t = 0; t < 9; t++) {
                int p  = nn * 9 + t;
                int x0 = s_xi[p], y0 = s_yi[p];
                float wx = s_wx[p], wy = s_wy[p];
                int x0c = min(max(x0, 0), 55),     x1c = min(max(x0 + 1, 0), 55);
                int y0c = min(max(y0, 0), 55),     y1c = min(max(y0 + 1, 0), 55);
                bool vx0 = (unsigned)x0 < 56u,     vx1 = (unsigned)(x0 + 1) < 56u;
                bool vy0 = (unsigned)y0 < 56u,     vy1 = (unsigned)(y0 + 1) < 56u;
                float v00 = (vx0 && vy0) ? img[y0c * Ww + x0c] : 0.f;
                float v01 = (vx1 && vy0) ? img[y0c * Ww + x1c] : 0.f;
                float v10 = (vx0 && vy1) ? img[y1c * Ww + x0c] : 0.f;
                float v11 = (vx1 && vy1) ? img[y1c * Ww + x1c] : 0.f;
                s_patch[nn * Kdim + c * 9 + t] =
                      v00 * ((1.f - wx) * (1.f - wy))
                    + v01 * (wx * (1.f - wy))
                    + v10 * ((1.f - wx) * wy)
                    + v11 * (wx * wy);
            }
        }
    }
    __syncthreads();

    // GEMM: thread computes o0 = tid&127 and o0+128, for 8 nn (half = tid>>7)
    const int o0   = tid & 127;
    const int nnb  = (tid >> 7) * 8;
    const float* patch = s_patch + nnb * Kdim;

    float acc0[8] = {0,0,0,0,0,0,0,0};
    float acc1[8] = {0,0,0,0,0,0,0,0};
    const float2* wT = (const float2*)g_linwT;   // [k][128] float2

    for (int k = 0; k < Kdim; k += 4) {
        float4 pv[8];
        #pragma unroll
        for (int nn = 0; nn < 8; nn++)
            pv[nn] = *(const float4*)&patch[nn * Kdim + k];
        #pragma unroll
        for (int q = 0; q < 4; q++) {
            float2 wv = wT[(k + q) * 128 + o0];
            #pragma unroll
            for (int nn = 0; nn < 8; nn++) {
                float pq = (q == 0) ? pv[nn].x : (q == 1) ? pv[nn].y
                         : (q == 2) ? pv[nn].z : pv[nn].w;
                acc0[nn] = fmaf(pq, wv.x, acc0[nn]);
                acc1[nn] = fmaf(pq, wv.y, acc1[nn]);
            }
        }
    }
    const float bv0 = lin_b[o0];
    const float bv1 = lin_b[o0 + 128];
    #pragma unroll
    for (int nn = 0; nn < 8; nn++) {
        int ob = s_obase[nnb + nn];
        out[SCORE_OFF + ob + o0 * NHW]         = acc0[nn] + bv0;
        out[SCORE_OFF + ob + (o0 + 128) * NHW] = acc1[nn] + bv1;
    }
}

// ---------------------------------------------------------------------------
extern "C" void kernel_launch(void* const* d_in, const int* in_sizes, int n_in,
                              void* d_out, int out_size) {
    const float* x      = (const float*)d_in[0];
    const float* stn0_w = (const float*)d_in[1];
    const float* stn0_b = (const float*)d_in[2];
    const float* stn1_w = (const float*)d_in[3];
    const float* lin_w  = (const float*)d_in[4];
    const float* lin_b  = (const float*)d_in[5];
    const int*   check  = (const int*)d_in[6];
    float* out = (float*)d_out;

    cudaFuncSetAttribute(k_sample, cudaFuncAttributeMaxDynamicSharedMemorySize,
                         16 * Kdim * (int)sizeof(float));

    k_transpose<<<(Oo * Kdim + 255) / 256, 256>>>(lin_w);

    dim3 g1(56, 2, 8);
    k_conv1<<<g1, 256>>>(x, stn0_w, stn0_b);

    k_conv2<<<(Ntot + 255) / 256, 256>>>(stn1_w, check, out);

    k_sample<<<Ntot / 16, 256, 16 * Kdim * sizeof(float)>>>(x, lin_b, out);
}

// round 6
// speedup vs baseline: 1.5987x; 1.5561x over previous
#include <cuda_runtime.h>
#include <cuda_bf16.h>
#include <cstdint>

// ---------------------------------------------------------------------------
// Conv2d_STN: B=8, C=128, H=W=56, k=3, Ho=Wo=54, N=B*Ho*Wo=23328, O=256
// ---------------------------------------------------------------------------

#define Bsz   8
#define Cch   128
#define Hh    56
#define Ww    56
#define HW    3136
#define CHW   401408
#define Ho    54
#define NHW   2916
#define Ntot  23328
#define Oo    256
#define Kdim  1152
#define KSTEPS 144          // 1152 / 8

#define SCORE_OFF 0
#define DIFF_OFF  5971968
#define OUT_OFF   6111936
#define AUXX_OFF  6251904
#define AUXY_OFF  6461856

#define PATCH_LD 1156       // smem row stride (floats)

__device__ float g_h[Bsz * Cch * Hh * Ww];          // conv1 output (NCHW)
__device__ float g_xt[Bsz * Hh * Ww * Cch];         // x channels-last [b][y][x][c]
__device__ float2 g_wpk[KSTEPS * 32 * 32];          // lin_w packed in B-fragment order (tf32)

__device__ __forceinline__ float to_tf32(float v) {
    float r;
    asm("cvt.rna.tf32.f32 %0, %1;" : "=f"(r) : "f"(v));
    return r;
}

// ---------------- K_xt: NCHW -> NHWC transpose of x ------------------------
__global__ __launch_bounds__(256) void k_xt(const float* __restrict__ x) {
    __shared__ float s[Cch][Ww + 1];
    const int b = blockIdx.y, y = blockIdx.x;
    const int tid = threadIdx.x;
    for (int e = tid; e < Cch * Ww; e += 256) {
        int c = e / Ww, xc = e % Ww;
        s[c][xc] = x[((b * Cch + c) * Hh + y) * Ww + xc];
    }
    __syncthreads();
    for (int e = tid; e < Cch * Ww; e += 256) {
        int xc = e >> 7, c = e & 127;
        g_xt[((b * Hh + y) * Ww + xc) * Cch + c] = s[c][xc];
    }
}

// ---------------- K_packw: lin_w -> mma B-fragment layout (tf32) -----------
// K permutation: k' = t*128 + c  <->  orig k = c*9 + t.
__global__ void k_packw(const float* __restrict__ lin_w) {
    int idx = blockIdx.x * 256 + threadIdx.x;
    if (idx >= KSTEPS * 32 * 32) return;
    int lane  = idx & 31;
    int ntile = (idx >> 5) & 31;
    int ks    = idx >> 10;
    int q = lane & 3, n = ntile * 8 + (lane >> 2);
    int kp1 = ks * 8 + q, kp2 = kp1 + 4;
    float v1 = lin_w[n * Kdim + (kp1 & 127) * 9 + (kp1 >> 7)];
    float v2 = lin_w[n * Kdim + (kp2 & 127) * 9 + (kp2 >> 7)];
    g_wpk[idx] = make_float2(to_tf32(v1), to_tf32(v2));
}

// ---------------- K1: conv1 + bias + relu (scalar) -------------------------
__global__ __launch_bounds__(256) void k_conv1(const float* __restrict__ x,
                                               const float* __restrict__ w,
                                               const float* __restrict__ bias) {
    __shared__ float s_in[3][16][58];
    __shared__ float s_w[16][9][64];

    const int ho  = blockIdx.x;
    const int cog = blockIdx.y;
    const int b   = blockIdx.z;
    const int tid = threadIdx.x;
    const int co_l = tid & 31;
    const int wo0  = (tid >> 5) * 7;

    float acc0[7] = {0,0,0,0,0,0,0};
    float acc1[7] = {0,0,0,0,0,0,0};

    for (int ci0 = 0; ci0 < Cch; ci0 += 16) {
        for (int e = tid; e < 3 * 16 * 58; e += 256) {
            int kh  = e / (16 * 58);
            int r   = e % (16 * 58);
            int ci  = r / 58;
            int col = r % 58;
            int y   = ho - 1 + kh;
            int xc  = col - 1;
            float v = 0.f;
            if ((unsigned)y < 56u && (unsigned)xc < 56u)
                v = x[((b * Cch + ci0 + ci) * Hh + y) * Ww + xc];
            s_in[kh][ci][col] = v;
        }
        for (int e = tid; e < 16 * 9 * 64; e += 256) {
            int ci = e / 576;
            int r  = e % 576;
            int t  = r >> 6;
            int co = r & 63;
            s_w[ci][t][co] = w[(cog * 64 + co) * Kdim + (ci0 + ci) * 9 + t];
        }
        __syncthreads();

        #pragma unroll 2
        for (int ci = 0; ci < 16; ci++) {
            float wr0[9], wr1[9];
            #pragma unroll
            for (int t = 0; t < 9; t++) {
                wr0[t] = s_w[ci][t][co_l];
                wr1[t] = s_w[ci][t][co_l + 32];
            }
            #pragma unroll
            for (int kh = 0; kh < 3; kh++) {
                float xv[9];
                #pragma unroll
                for (int u = 0; u < 9; u++) xv[u] = s_in[kh][ci][wo0 + u];
                #pragma unroll
                for (int kw = 0; kw < 3; kw++) {
                    float w0 = wr0[kh * 3 + kw];
                    float w1 = wr1[kh * 3 + kw];
                    #pragma unroll
                    for (int u = 0; u < 7; u++) {
                        acc0[u] = fmaf(xv[u + kw], w0, acc0[u]);
                        acc1[u] = fmaf(xv[u + kw], w1, acc1[u]);
                    }
                }
            }
        }
        __syncthreads();
    }

    const float bv0 = bias[cog * 64 + co_l];
    const float bv1 = bias[cog * 64 + co_l + 32];
    float* s_out = &s_w[0][0][0];
    #pragma unroll
    for (int u = 0; u < 7; u++) {
        s_out[co_l * 56 + wo0 + u]        = fmaxf(acc0[u] + bv0, 0.f);
        s_out[(co_l + 32) * 56 + wo0 + u] = fmaxf(acc1[u] + bv1, 0.f);
    }
    __syncthreads();
    for (int e = tid; e < 64 * 56; e += 256) {
        int col = e / 56, wo = e % 56;
        g_h[((b * Cch + cog * 64 + col) * Hh + ho) * Ww + wo] = s_out[e];
    }
}

// ---------------- K2: conv2 (valid) -> theta / out / diff / auxx / auxy ----
__global__ __launch_bounds__(256) void k_conv2(const float* __restrict__ w1,
                                               const int* __restrict__ check,
                                               float* __restrict__ out) {
    __shared__ float s_w[128][9][6];
    for (int e = threadIdx.x; e < 128 * 54; e += 256) {
        int c = e / 54, r = e % 54, t = r / 6, ch = r % 6;
        s_w[c][t][ch] = w1[ch * Kdim + c * 9 + t];
    }
    __syncthreads();

    int n = blockIdx.x * 256 + threadIdx.x;
    if (n >= Ntot) return;
    int b = n / NHW, r = n % NHW, wo = r / Ho, ho = r % Ho;

    float acc[6] = {0,0,0,0,0,0};
    const float* hb = g_h + b * CHW;
    for (int c = 0; c < Cch; c++) {
        const float* hc = hb + c * HW;
        #pragma unroll
        for (int i = 0; i < 3; i++) {
            #pragma unroll
            for (int j = 0; j < 3; j++) {
                float hv = hc[(ho + i) * Ww + wo + j];
                #pragma unroll
                for (int ch = 0; ch < 6; ch++)
                    acc[ch] = fmaf(hv, s_w[c][i * 3 + j][ch], acc[ch]);
            }
        }
    }

    const float scale = 1.0f - (float)check[0];
    const float ident6[6] = {1.f, 0.f, 0.f, 0.f, 1.f, 0.f};
    float th[6];
    #pragma unroll
    for (int ch = 0; ch < 6; ch++) {
        float cv = acc[ch] * scale;
        th[ch] = cv + ident6[ch];
        out[OUT_OFF  + ((b * 6 + ch) * Ho + ho) * Ho + wo] = th[ch];
        out[DIFF_OFF + n * 6 + ch] = -cv;
    }

    #pragma unroll
    for (int i = 0; i < 3; i++) {
        float bi = (2.f * (float)i + 1.f) / 3.f - 1.f;
        #pragma unroll
        for (int j = 0; j < 3; j++) {
            float bj = (2.f * (float)j + 1.f) / 3.f - 1.f;
            float gx = th[0] * bj + th[1] * bi + th[2];
            float gy = th[3] * bj + th[4] * bi + th[5];
            out[AUXX_OFF + n * 9 + i * 3 + j] =
                (gx + 1.0f + (float)wo) * (2.0f / 55.0f) - 1.0f;
            out[AUXY_OFF + n * 9 + i * 3 + j] =
                (gy + 1.0f + (float)ho) * (2.0f / 55.0f) - 1.0f;
        }
    }
}

// ---------------- K3: coalesced gather (NHWC) + tf32 tensor GEMM -----------
__global__ __launch_bounds__(256) void k_sample(const float* __restrict__ lin_b,
                                                float* __restrict__ out) {
    extern __shared__ float s_patch[];          // [32][PATCH_LD]
    __shared__ int   s_xi[288], s_yi[288];
    __shared__ float s_wx[288], s_wy[288];
    __shared__ int   s_xtoff[32], s_obase[32];

    const int tid  = threadIdx.x;
    const int lane = tid & 31;
    const int wrp  = tid >> 5;
    const int n0   = blockIdx.x * 32;

    if (tid < 32) {
        int n = n0 + tid;
        int b = n / NHW, r = n % NHW, wo = r / Ho, ho = r % Ho;
        s_xtoff[tid] = b * (Hh * Ww * Cch);
        s_obase[tid] = b * (Oo * NHW) + ho * Ho + wo;
    }
    // FIX (R4 bug): 288 tasks > 256 threads -> must stride
    for (int e = tid; e < 288; e += 256) {
        int nn = e / 9, t = e % 9;
        int n = n0 + nn;
        float ax = out[AUXX_OFF + n * 9 + t];
        float ay = out[AUXY_OFF + n * 9 + t];
        float gx = (ax + 1.0f) * 28.0f - 0.5f;
        float gy = (ay + 1.0f) * 28.0f - 0.5f;
        float x0f = floorf(gx), y0f = floorf(gy);
        s_xi[e] = (int)x0f;  s_yi[e] = (int)y0f;
        s_wx[e] = gx - x0f;  s_wy[e] = gy - y0f;
    }
    __syncthreads();

    // gather: warp handles tasks wrp, wrp+8, ...; lane covers 4 channels
    for (int task = wrp; task < 288; task += 8) {
        const int nn = task / 9, t = task % 9;
        const int x0 = s_xi[task], y0 = s_yi[task];
        const float wx = s_wx[task], wy = s_wy[task];
        const float w00 = (1.f - wx) * (1.f - wy);
        const float w01 = wx * (1.f - wy);
        const float w10 = (1.f - wx) * wy;
        const float w11 = wx * wy;
        const bool vx0 = (unsigned)x0 < 56u, vx1 = (unsigned)(x0 + 1) < 56u;
        const bool vy0 = (unsigned)y0 < 56u, vy1 = (unsigned)(y0 + 1) < 56u;
        const float* base = g_xt + s_xtoff[nn] + lane * 4;
        const float4 z = make_float4(0.f, 0.f, 0.f, 0.f);
        float4 v00 = (vy0 && vx0) ? *(const float4*)(base + (y0 * Ww + x0) * Cch) : z;
        float4 v01 = (vy0 && vx1) ? *(const float4*)(base + (y0 * Ww + x0 + 1) * Cch) : z;
        float4 v10 = (vy1 && vx0) ? *(const float4*)(base + ((y0 + 1) * Ww + x0) * Cch) : z;
        float4 v11 = (vy1 && vx1) ? *(const float4*)(base + ((y0 + 1) * Ww + x0 + 1) * Cch) : z;
        float4 v;
        v.x = to_tf32(v00.x * w00 + v01.x * w01 + v10.x * w10 + v11.x * w11);
        v.y = to_tf32(v00.y * w00 + v01.y * w01 + v10.y * w10 + v11.y * w11);
        v.z = to_tf32(v00.z * w00 + v01.z * w01 + v10.z * w10 + v11.z * w11);
        v.w = to_tf32(v00.w * w00 + v01.w * w01 + v10.w * w10 + v11.w * w11);
        *(float4*)&s_patch[nn * PATCH_LD + t * 128 + lane * 4] = v;
    }
    __syncthreads();

    // GEMM: warp = m16 (wrp&1) x n64 ((wrp>>1)*8 n8-tiles)
    const int mrow = (wrp & 1) * 16;
    const int nt0  = (wrp >> 1) * 8;
    const int r    = lane >> 2;
    const int q    = lane & 3;

    float acc[8][4];
    #pragma unroll
    for (int i = 0; i < 8; i++)
        #pragma unroll
        for (int j = 0; j < 4; j++) acc[i][j] = 0.f;

    const float2* __restrict__ wpk = g_wpk;
    const float* pa  = s_patch + (mrow + r) * PATCH_LD + q;
    const float* pa8 = pa + 8 * PATCH_LD;

    for (int ks = 0; ks < KSTEPS; ks++) {
        uint32_t a0 = __float_as_uint(pa [ks * 8]);
        uint32_t a1 = __float_as_uint(pa8[ks * 8]);
        uint32_t a2 = __float_as_uint(pa [ks * 8 + 4]);
        uint32_t a3 = __float_as_uint(pa8[ks * 8 + 4]);
        const float2* wp = wpk + (ks * 32 + nt0) * 32 + lane;
        #pragma unroll
        for (int i = 0; i < 8; i++) {
            float2 bv = wp[i * 32];
            uint32_t b0 = __float_as_uint(bv.x);
            uint32_t b1 = __float_as_uint(bv.y);
            asm volatile(
                "mma.sync.aligned.m16n8k8.row.col.f32.tf32.tf32.f32 "
                "{%0,%1,%2,%3}, {%4,%5,%6,%7}, {%8,%9}, {%0,%1,%2,%3};"
                : "+f"(acc[i][0]), "+f"(acc[i][1]), "+f"(acc[i][2]), "+f"(acc[i][3])
                : "r"(a0), "r"(a1), "r"(a2), "r"(a3), "r"(b0), "r"(b1));
        }
    }

    #pragma unroll
    for (int i = 0; i < 8; i++) {
        int o0 = (nt0 + i) * 8 + q * 2;
        float b0 = __ldg(&lin_b[o0]);
        float b1 = __ldg(&lin_b[o0 + 1]);
        int nnA = mrow + r, nnB = nnA + 8;
        out[SCORE_OFF + s_obase[nnA] + o0 * NHW]       = acc[i][0] + b0;
        out[SCORE_OFF + s_obase[nnA] + (o0 + 1) * NHW] = acc[i][1] + b1;
        out[SCORE_OFF + s_obase[nnB] + o0 * NHW]       = acc[i][2] + b0;
        out[SCORE_OFF + s_obase[nnB] + (o0 + 1) * NHW] = acc[i][3] + b1;
    }
}

// ---------------------------------------------------------------------------
extern "C" void kernel_launch(void* const* d_in, const int* in_sizes, int n_in,
                              void* d_out, int out_size) {
    const float* x      = (const float*)d_in[0];
    const float* stn0_w = (const float*)d_in[1];
    const float* stn0_b = (const float*)d_in[2];
    const float* stn1_w = (const float*)d_in[3];
    const float* lin_w  = (const float*)d_in[4];
    const float* lin_b  = (const float*)d_in[5];
    const int*   check  = (const int*)d_in[6];
    float* out = (float*)d_out;

    const int smem_bytes = 32 * PATCH_LD * (int)sizeof(float);
    cudaFuncSetAttribute(k_sample, cudaFuncAttributeMaxDynamicSharedMemorySize,
                         smem_bytes);

    dim3 gxt(Hh, Bsz);
    k_xt<<<gxt, 256>>>(x);

    k_packw<<<(KSTEPS * 32 * 32 + 255) / 256, 256>>>(lin_w);

    dim3 g1(56, 2, 8);
    k_conv1<<<g1, 256>>>(x, stn0_w, stn0_b);

    k_conv2<<<(Ntot + 255) / 256, 256>>>(stn1_w, check, out);

    k_sample<<<Ntot / 32, 256, smem_bytes>>>(lin_b, out);
}

// round 7
// speedup vs baseline: 2.3490x; 1.4693x over previous
#include <cuda_runtime.h>
#include <cuda_bf16.h>
#include <cstdint>

// ---------------------------------------------------------------------------
// Conv2d_STN: B=8, C=128, H=W=56, k=3, Ho=Wo=54, N=B*Ho*Wo=23328, O=256
// ---------------------------------------------------------------------------

#define Bsz   8
#define Cch   128
#define Hh    56
#define Ww    56
#define HW    3136
#define Ho    54
#define NHW   2916
#define Ntot  23328
#define Npix  25088         // 8*56*56
#define Oo    256
#define Kdim  1152
#define KSTEPS 144          // 1152 / 8

#define SCORE_OFF 0
#define DIFF_OFF  5971968
#define OUT_OFF   6111936
#define AUXX_OFF  6251904
#define AUXY_OFF  6461856

#define PATCH_LD 1156       // smem row stride (floats), conflict-free a-frag reads

__device__ float  g_xt[Bsz * Hh * Ww * Cch];        // x channels-last [b][y][x][c]
__device__ float  g_ht[Npix * Cch];                 // conv1 out channels-last [b][y][x][co]
__device__ float2 g_wpk[KSTEPS * 32 * 32];          // lin_w   packed B-frags (tf32), 32 n-tiles
__device__ float2 g_w0pk[KSTEPS * 16 * 32];         // stn0_w  packed B-frags (tf32), 16 n-tiles

__device__ __forceinline__ float to_tf32(float v) {
    float r;
    asm("cvt.rna.tf32.f32 %0, %1;" : "=f"(r) : "f"(v));
    return r;
}

// ---------------- K_xt: NCHW -> NHWC transpose of x ------------------------
__global__ __launch_bounds__(256) void k_xt(const float* __restrict__ x) {
    __shared__ float s[Cch][Ww + 1];
    const int b = blockIdx.y, y = blockIdx.x;
    const int tid = threadIdx.x;
    for (int e = tid; e < Cch * Ww; e += 256) {
        int c = e / Ww, xc = e % Ww;
        s[c][xc] = x[((b * Cch + c) * Hh + y) * Ww + xc];
    }
    __syncthreads();
    for (int e = tid; e < Cch * Ww; e += 256) {
        int xc = e >> 7, c = e & 127;
        g_xt[((b * Hh + y) * Ww + xc) * Cch + c] = s[c][xc];
    }
}

// ---------------- K_packw: weight -> mma B-fragment layout (tf32) ----------
// K permutation: k' = t*128 + c  <->  orig k = c*9 + t. Row stride Kdim both.
// dst[(ks*ntiles + ntile)*32 + lane] = { B[ks*8+q][n], B[ks*8+4+q][n] },
//   q = lane&3, n = ntile*8 + lane>>2.
__global__ void k_packw(const float* __restrict__ w, float2* __restrict__ dst,
                        int ntiles) {
    int idx = blockIdx.x * 256 + threadIdx.x;
    if (idx >= KSTEPS * ntiles * 32) return;
    int lane  = idx & 31;
    int ntile = (idx >> 5) % ntiles;
    int ks    = (idx >> 5) / ntiles;
    int q = lane & 3, n = ntile * 8 + (lane >> 2);
    int kp1 = ks * 8 + q, kp2 = kp1 + 4;
    float v1 = w[n * Kdim + (kp1 & 127) * 9 + (kp1 >> 7)];
    float v2 = w[n * Kdim + (kp2 & 127) * 9 + (kp2 >> 7)];
    dst[idx] = make_float2(to_tf32(v1), to_tf32(v2));
}

// ---------------- K1: conv1 as implicit-GEMM tf32 mma ----------------------
// block = 32 consecutive pixels, 256 threads. im2col from g_xt (zero pad).
// Output: g_ht channels-last with bias + relu.
__global__ __launch_bounds__(256) void k_conv1m(const float* __restrict__ bias) {
    extern __shared__ float s_patch[];          // [32][PATCH_LD]
    __shared__ int s_b[32], s_y[32], s_x[32];

    const int tid  = threadIdx.x;
    const int lane = tid & 31;
    const int wrp  = tid >> 5;
    const int p0   = blockIdx.x * 32;

    if (tid < 32) {
        int p = p0 + tid;
        int b = p / HW, rr = p % HW;
        s_b[tid] = b; s_y[tid] = rr / Ww; s_x[tid] = rr % Ww;
    }
    __syncthreads();

    // gather: 288 tasks (32 px x 9 taps), warp-strided, lane = 4 channels
    for (int task = wrp; task < 288; task += 8) {
        const int nn = task / 9, t = task % 9;
        const int kh = t / 3, kw = t % 3;
        const int yy = s_y[nn] + kh - 1;
        const int xx = s_x[nn] + kw - 1;
        float4 v = make_float4(0.f, 0.f, 0.f, 0.f);
        if ((unsigned)yy < 56u && (unsigned)xx < 56u)
            v = *(const float4*)&g_xt[(((s_b[nn] * Hh) + yy) * Ww + xx) * Cch + lane * 4];
        v.x = to_tf32(v.x); v.y = to_tf32(v.y);
        v.z = to_tf32(v.z); v.w = to_tf32(v.w);
        *(float4*)&s_patch[nn * PATCH_LD + t * 128 + lane * 4] = v;
    }
    __syncthreads();

    // GEMM: warp = m16 (wrp&1) x n32 ((wrp>>1)*4 n8-tiles), N=128 total
    const int mrow = (wrp & 1) * 16;
    const int nt0  = (wrp >> 1) * 4;
    const int r    = lane >> 2;
    const int q    = lane & 3;

    float acc[4][4];
    #pragma unroll
    for (int i = 0; i < 4; i++)
        #pragma unroll
        for (int j = 0; j < 4; j++) acc[i][j] = 0.f;

    const float* pa  = s_patch + (mrow + r) * PATCH_LD + q;
    const float* pa8 = pa + 8 * PATCH_LD;

    for (int ks = 0; ks < KSTEPS; ks++) {
        uint32_t a0 = __float_as_uint(pa [ks * 8]);
        uint32_t a1 = __float_as_uint(pa8[ks * 8]);
        uint32_t a2 = __float_as_uint(pa [ks * 8 + 4]);
        uint32_t a3 = __float_as_uint(pa8[ks * 8 + 4]);
        const float2* wp = g_w0pk + (ks * 16 + nt0) * 32 + lane;
        #pragma unroll
        for (int i = 0; i < 4; i++) {
            float2 bv = wp[i * 32];
            uint32_t b0 = __float_as_uint(bv.x);
            uint32_t b1 = __float_as_uint(bv.y);
            asm volatile(
                "mma.sync.aligned.m16n8k8.row.col.f32.tf32.tf32.f32 "
                "{%0,%1,%2,%3}, {%4,%5,%6,%7}, {%8,%9}, {%0,%1,%2,%3};"
                : "+f"(acc[i][0]), "+f"(acc[i][1]), "+f"(acc[i][2]), "+f"(acc[i][3])
                : "r"(a0), "r"(a1), "r"(a2), "r"(a3), "r"(b0), "r"(b1));
        }
    }

    #pragma unroll
    for (int i = 0; i < 4; i++) {
        int o0 = (nt0 + i) * 8 + q * 2;
        float b0 = __ldg(&bias[o0]);
        float b1 = __ldg(&bias[o0 + 1]);
        int pA = p0 + mrow + r, pB = pA + 8;
        float2 vA = make_float2(fmaxf(acc[i][0] + b0, 0.f), fmaxf(acc[i][1] + b1, 0.f));
        float2 vB = make_float2(fmaxf(acc[i][2] + b0, 0.f), fmaxf(acc[i][3] + b1, 0.f));
        *(float2*)&g_ht[pA * Cch + o0] = vA;
        *(float2*)&g_ht[pB * Cch + o0] = vB;
    }
}

// ---------------- K2: conv2 warp-per-pixel on channels-last h --------------
__global__ __launch_bounds__(256) void k_conv2(const float* __restrict__ w1,
                                               const int* __restrict__ check,
                                               float* __restrict__ out) {
    __shared__ float s_w[9 * 6 * 128];     // [t][ch][c]
    const int tid  = threadIdx.x;
    const int lane = tid & 31;
    const int wrp  = tid >> 5;

    for (int e = tid; e < 9 * 6 * 128; e += 256) {
        int c = e & 127, tc = e >> 7;
        int t = tc / 6, ch = tc % 6;
        s_w[e] = w1[ch * Kdim + c * 9 + t];
    }
    __syncthreads();

    const int n  = blockIdx.x * 8 + wrp;          // < 23328 always (2916*8)
    const int b  = n / NHW, r = n % NHW;
    const int wo = r / Ho, ho = r % Ho;

    float acc[6] = {0,0,0,0,0,0};
    const float* hb = g_ht + ((b * Hh + ho) * Ww + wo) * Cch + lane * 4;
    #pragma unroll
    for (int i = 0; i < 3; i++) {
        #pragma unroll
        for (int j = 0; j < 3; j++) {
            float4 hv = *(const float4*)&hb[(i * Ww + j) * Cch];
            const int t = i * 3 + j;
            #pragma unroll
            for (int ch = 0; ch < 6; ch++) {
                float4 wv = *(const float4*)&s_w[(t * 6 + ch) * 128 + lane * 4];
                acc[ch] += hv.x * wv.x + hv.y * wv.y + hv.z * wv.z + hv.w * wv.w;
            }
        }
    }
    #pragma unroll
    for (int ch = 0; ch < 6; ch++) {
        #pragma unroll
        for (int off = 16; off > 0; off >>= 1)
            acc[ch] += __shfl_xor_sync(0xFFFFFFFFu, acc[ch], off);
    }

    const float scale = 1.0f - (float)check[0];
    const float ident6[6] = {1.f, 0.f, 0.f, 0.f, 1.f, 0.f};
    float th[6];
    #pragma unroll
    for (int ch = 0; ch < 6; ch++) th[ch] = acc[ch] * scale + ident6[ch];

    if (lane < 6) {
        out[OUT_OFF  + ((b * 6 + lane) * Ho + ho) * Ho + wo] = th[lane];
        out[DIFF_OFF + n * 6 + lane] = -(acc[lane] * scale);
    }
    if (lane < 9) {
        int i = lane / 3, j = lane % 3;
        float bi = (2.f * (float)i + 1.f) / 3.f - 1.f;
        float bj = (2.f * (float)j + 1.f) / 3.f - 1.f;
        float gx = th[0] * bj + th[1] * bi + th[2];
        float gy = th[3] * bj + th[4] * bi + th[5];
        out[AUXX_OFF + n * 9 + lane] = (gx + 1.0f + (float)wo) * (2.0f / 55.0f) - 1.0f;
        out[AUXY_OFF + n * 9 + lane] = (gy + 1.0f + (float)ho) * (2.0f / 55.0f) - 1.0f;
    }
}

// ---------------- K3: coalesced gather (NHWC) + tf32 tensor GEMM -----------
__global__ __launch_bounds__(256) void k_sample(const float* __restrict__ lin_b,
                                                float* __restrict__ out) {
    extern __shared__ float s_patch[];          // [32][PATCH_LD]
    __shared__ int   s_xi[288], s_yi[288];
    __shared__ float s_wx[288], s_wy[288];
    __shared__ int   s_xtoff[32], s_obase[32];

    const int tid  = threadIdx.x;
    const int lane = tid & 31;
    const int wrp  = tid >> 5;
    const int n0   = blockIdx.x * 32;

    if (tid < 32) {
        int n = n0 + tid;
        int b = n / NHW, r = n % NHW, wo = r / Ho, ho = r % Ho;
        s_xtoff[tid] = b * (Hh * Ww * Cch);
        s_obase[tid] = b * (Oo * NHW) + ho * Ho + wo;
    }
    for (int e = tid; e < 288; e += 256) {
        int nn = e / 9, t = e % 9;
        int n = n0 + nn;
        float ax = out[AUXX_OFF + n * 9 + t];
        float ay = out[AUXY_OFF + n * 9 + t];
        float gx = (ax + 1.0f) * 28.0f - 0.5f;
        float gy = (ay + 1.0f) * 28.0f - 0.5f;
        float x0f = floorf(gx), y0f = floorf(gy);
        s_xi[e] = (int)x0f;  s_yi[e] = (int)y0f;
        s_wx[e] = gx - x0f;  s_wy[e] = gy - y0f;
    }
    __syncthreads();

    for (int task = wrp; task < 288; task += 8) {
        const int nn = task / 9, t = task % 9;
        const int x0 = s_xi[task], y0 = s_yi[task];
        const float wx = s_wx[task], wy = s_wy[task];
        const float w00 = (1.f - wx) * (1.f - wy);
        const float w01 = wx * (1.f - wy);
        const float w10 = (1.f - wx) * wy;
        const float w11 = wx * wy;
        const bool vx0 = (unsigned)x0 < 56u, vx1 = (unsigned)(x0 + 1) < 56u;
        const bool vy0 = (unsigned)y0 < 56u, vy1 = (unsigned)(y0 + 1) < 56u;
        const float* base = g_xt + s_xtoff[nn] + lane * 4;
        const float4 z = make_float4(0.f, 0.f, 0.f, 0.f);
        float4 v00 = (vy0 && vx0) ? *(const float4*)(base + (y0 * Ww + x0) * Cch) : z;
        float4 v01 = (vy0 && vx1) ? *(const float4*)(base + (y0 * Ww + x0 + 1) * Cch) : z;
        float4 v10 = (vy1 && vx0) ? *(const float4*)(base + ((y0 + 1) * Ww + x0) * Cch) : z;
        float4 v11 = (vy1 && vx1) ? *(const float4*)(base + ((y0 + 1) * Ww + x0 + 1) * Cch) : z;
        float4 v;
        v.x = to_tf32(v00.x * w00 + v01.x * w01 + v10.x * w10 + v11.x * w11);
        v.y = to_tf32(v00.y * w00 + v01.y * w01 + v10.y * w10 + v11.y * w11);
        v.z = to_tf32(v00.z * w00 + v01.z * w01 + v10.z * w10 + v11.z * w11);
        v.w = to_tf32(v00.w * w00 + v01.w * w01 + v10.w * w10 + v11.w * w11);
        *(float4*)&s_patch[nn * PATCH_LD + t * 128 + lane * 4] = v;
    }
    __syncthreads();

    const int mrow = (wrp & 1) * 16;
    const int nt0  = (wrp >> 1) * 8;
    const int r    = lane >> 2;
    const int q    = lane & 3;

    float acc[8][4];
    #pragma unroll
    for (int i = 0; i < 8; i++)
        #pragma unroll
        for (int j = 0; j < 4; j++) acc[i][j] = 0.f;

    const float* pa  = s_patch + (mrow + r) * PATCH_LD + q;
    const float* pa8 = pa + 8 * PATCH_LD;

    for (int ks = 0; ks < KSTEPS; ks++) {
        uint32_t a0 = __float_as_uint(pa [ks * 8]);
        uint32_t a1 = __float_as_uint(pa8[ks * 8]);
        uint32_t a2 = __float_as_uint(pa [ks * 8 + 4]);
        uint32_t a3 = __float_as_uint(pa8[ks * 8 + 4]);
        const float2* wp = g_wpk + (ks * 32 + nt0) * 32 + lane;
        #pragma unroll
        for (int i = 0; i < 8; i++) {
            float2 bv = wp[i * 32];
            uint32_t b0 = __float_as_uint(bv.x);
            uint32_t b1 = __float_as_uint(bv.y);
            asm volatile(
                "mma.sync.aligned.m16n8k8.row.col.f32.tf32.tf32.f32 "
                "{%0,%1,%2,%3}, {%4,%5,%6,%7}, {%8,%9}, {%0,%1,%2,%3};"
                : "+f"(acc[i][0]), "+f"(acc[i][1]), "+f"(acc[i][2]), "+f"(acc[i][3])
                : "r"(a0), "r"(a1), "r"(a2), "r"(a3), "r"(b0), "r"(b1));
        }
    }

    #pragma unroll
    for (int i = 0; i < 8; i++) {
        int o0 = (nt0 + i) * 8 + q * 2;
        float b0 = __ldg(&lin_b[o0]);
        float b1 = __ldg(&lin_b[o0 + 1]);
        int nnA = mrow + r, nnB = nnA + 8;
        out[SCORE_OFF + s_obase[nnA] + o0 * NHW]       = acc[i][0] + b0;
        out[SCORE_OFF + s_obase[nnA] + (o0 + 1) * NHW] = acc[i][1] + b1;
        out[SCORE_OFF + s_obase[nnB] + o0 * NHW]       = acc[i][2] + b0;
        out[SCORE_OFF + s_obase[nnB] + (o0 + 1) * NHW] = acc[i][3] + b1;
    }
}

// ---------------------------------------------------------------------------
extern "C" void kernel_launch(void* const* d_in, const int* in_sizes, int n_in,
                              void* d_out, int out_size) {
    const float* x      = (const float*)d_in[0];
    const float* stn0_w = (const float*)d_in[1];
    const float* stn0_b = (const float*)d_in[2];
    const float* stn1_w = (const float*)d_in[3];
    const float* lin_w  = (const float*)d_in[4];
    const float* lin_b  = (const float*)d_in[5];
    const int*   check  = (const int*)d_in[6];
    float* out = (float*)d_out;

    const int smem_bytes = 32 * PATCH_LD * (int)sizeof(float);
    cudaFuncSetAttribute(k_sample, cudaFuncAttributeMaxDynamicSharedMemorySize,
                         smem_bytes);
    cudaFuncSetAttribute(k_conv1m, cudaFuncAttributeMaxDynamicSharedMemorySize,
                         smem_bytes);

    float2* wpk;  cudaGetSymbolAddress((void**)&wpk,  g_wpk);
    float2* w0pk; cudaGetSymbolAddress((void**)&w0pk, g_w0pk);

    dim3 gxt(Hh, Bsz);
    k_xt<<<gxt, 256>>>(x);

    k_packw<<<(KSTEPS * 32 * 32 + 255) / 256, 256>>>(lin_w, wpk, 32);
    k_packw<<<(KSTEPS * 16 * 32 + 255) / 256, 256>>>(stn0_w, w0pk, 16);

    k_conv1m<<<Npix / 32, 256, smem_bytes>>>(stn0_b);

    k_conv2<<<Ntot / 8, 256>>>(stn1_w, check, out);

    k_sample<<<Ntot / 32, 256, smem_bytes>>>(lin_b, out);
}

// round 10
// speedup vs baseline: 3.5523x; 1.5123x over previous
#include <cuda_runtime.h>
#include <cuda_bf16.h>
#include <cstdint>

// ---------------------------------------------------------------------------
// Conv2d_STN: B=8, C=128, H=W=56, k=3, Ho=Wo=54, N=B*Ho*Wo=23328, O=256
// K streamed per-tap: k' = t*128 + c, double-buffered [32][132] tiles.
// ---------------------------------------------------------------------------

#define Bsz   8
#define Cch   128
#define Hh    56
#define Ww    56
#define HW    3136
#define Ho    54
#define NHW   2916
#define Ntot  23328
#define Npix  25088         // 8*56*56
#define Oo    256
#define Kdim  1152
#define KSTEPS 144          // 1152 / 8

#define SCORE_OFF 0
#define DIFF_OFF  5971968
#define OUT_OFF   6111936
#define AUXX_OFF  6251904
#define AUXY_OFF  6461856

#define CH_LD   132                  // chunk row stride (floats); (4r+q)%32 distinct
#define CH_SZ   (32 * CH_LD)         // one tap tile
#define SMEM_B  (2 * CH_SZ * 4)      // dynamic smem bytes (33792)

__device__ float  g_xt[Bsz * Hh * Ww * Cch];        // x channels-last [b][y][x][c]
__device__ float  g_ht[Npix * Cch];                 // conv1 out channels-last
__device__ float2 g_wpk[KSTEPS * 32 * 32];          // lin_w  packed B-frags (tf32)
__device__ float2 g_w0pk[KSTEPS * 16 * 32];         // stn0_w packed B-frags (tf32)

__device__ __forceinline__ float to_tf32(float v) {
    float r;
    asm("cvt.rna.tf32.f32 %0, %1;" : "=f"(r) : "f"(v));
    return r;
}

#define MMA(acc, a0, a1, a2, a3, b0, b1)                                       \
    asm volatile(                                                              \
        "mma.sync.aligned.m16n8k8.row.col.f32.tf32.tf32.f32 "                  \
        "{%0,%1,%2,%3}, {%4,%5,%6,%7}, {%8,%9}, {%0,%1,%2,%3};"                \
        : "+f"(acc[0]), "+f"(acc[1]), "+f"(acc[2]), "+f"(acc[3])               \
        : "r"(a0), "r"(a1), "r"(a2), "r"(a3), "r"(b0), "r"(b1))

// ---------------- K_xt: NCHW -> NHWC transpose of x ------------------------
__global__ __launch_bounds__(256) void k_xt(const float* __restrict__ x) {
    __shared__ float s[Cch][Ww + 1];
    const int b = blockIdx.y, y = blockIdx.x;
    const int tid = threadIdx.x;
    for (int e = tid; e < Cch * Ww; e += 256) {
        int c = e / Ww, xc = e % Ww;
        s[c][xc] = x[((b * Cch + c) * Hh + y) * Ww + xc];
    }
    __syncthreads();
    for (int e = tid; e < Cch * Ww; e += 256) {
        int xc = e >> 7, c = e & 127;
        g_xt[((b * Hh + y) * Ww + xc) * Cch + c] = s[c][xc];
    }
}

// ---------------- K_packw: weight -> mma B-fragment layout (tf32) ----------
__global__ void k_packw(const float* __restrict__ w, float2* __restrict__ dst,
                        int ntiles) {
    int idx = blockIdx.x * 256 + threadIdx.x;
    if (idx >= KSTEPS * ntiles * 32) return;
    int lane  = idx & 31;
    int ntile = (idx >> 5) % ntiles;
    int ks    = (idx >> 5) / ntiles;
    int q = lane & 3, n = ntile * 8 + (lane >> 2);
    int kp1 = ks * 8 + q, kp2 = kp1 + 4;
    float v1 = w[n * Kdim + (kp1 & 127) * 9 + (kp1 >> 7)];
    float v2 = w[n * Kdim + (kp2 & 127) * 9 + (kp2 >> 7)];
    dst[idx] = make_float2(to_tf32(v1), to_tf32(v2));
}

// ---------------- K1: conv1 implicit-GEMM, tap-streamed --------------------
__global__ __launch_bounds__(256) void k_conv1m(const float* __restrict__ bias) {
    extern __shared__ float s_buf[];            // [2][32][CH_LD]
    __shared__ int s_b[32], s_y[32], s_x[32];

    const int tid  = threadIdx.x;
    const int lane = tid & 31;
    const int wrp  = tid >> 5;
    const int p0   = blockIdx.x * 32;

    if (tid < 32) {
        int p = p0 + tid;
        int b = p / HW, rr = p % HW;
        s_b[tid] = b; s_y[tid] = rr / Ww; s_x[tid] = rr % Ww;
    }
    __syncthreads();

    const int mrow = (wrp & 1) * 16;
    const int nt0  = (wrp >> 1) * 4;
    const int r    = lane >> 2;
    const int q    = lane & 3;

    float acc[4][4];
    #pragma unroll
    for (int i = 0; i < 4; i++)
        #pragma unroll
        for (int j = 0; j < 4; j++) acc[i][j] = 0.f;

    // gather tap t into buf: warp -> 4 pixels, lane -> 4 channels
    auto gather = [&](int t, float* buf) {
        const int kh = t / 3, kw = t % 3;
        #pragma unroll
        for (int i = 0; i < 4; i++) {
            const int nn = wrp * 4 + i;
            const int yy = s_y[nn] + kh - 1;
            const int xx = s_x[nn] + kw - 1;
            float4 v = make_float4(0.f, 0.f, 0.f, 0.f);
            if ((unsigned)yy < 56u && (unsigned)xx < 56u)
                v = *(const float4*)&g_xt[(((s_b[nn] * Hh) + yy) * Ww + xx) * Cch + lane * 4];
            v.x = to_tf32(v.x); v.y = to_tf32(v.y);
            v.z = to_tf32(v.z); v.w = to_tf32(v.w);
            *(float4*)&buf[nn * CH_LD + lane * 4] = v;
        }
    };

    gather(0, s_buf);
    __syncthreads();

    for (int t = 0; t < 9; t++) {
        float* cur = s_buf + (t & 1) * CH_SZ;
        if (t < 8) gather(t + 1, s_buf + ((t + 1) & 1) * CH_SZ);

        const float* pa  = cur + (mrow + r) * CH_LD + q;
        const float* pa8 = pa + 8 * CH_LD;
        #pragma unroll 4
        for (int ksl = 0; ksl < 16; ksl++) {
            uint32_t a0 = __float_as_uint(pa [ksl * 8]);
            uint32_t a1 = __float_as_uint(pa8[ksl * 8]);
            uint32_t a2 = __float_as_uint(pa [ksl * 8 + 4]);
            uint32_t a3 = __float_as_uint(pa8[ksl * 8 + 4]);
            const float2* wp = g_w0pk + (((t * 16 + ksl) * 16) + nt0) * 32 + lane;
            #pragma unroll
            for (int i = 0; i < 4; i++) {
                float2 bv = wp[i * 32];
                MMA(acc[i], a0, a1, a2, a3,
                    __float_as_uint(bv.x), __float_as_uint(bv.y));
            }
        }
        __syncthreads();
    }

    #pragma unroll
    for (int i = 0; i < 4; i++) {
        int o0 = (nt0 + i) * 8 + q * 2;
        float b0 = __ldg(&bias[o0]);
        float b1 = __ldg(&bias[o0 + 1]);
        int pA = p0 + mrow + r, pB = pA + 8;
        float2 vA = make_float2(fmaxf(acc[i][0] + b0, 0.f), fmaxf(acc[i][1] + b1, 0.f));
        float2 vB = make_float2(fmaxf(acc[i][2] + b0, 0.f), fmaxf(acc[i][3] + b1, 0.f));
        *(float2*)&g_ht[pA * Cch + o0] = vA;
        *(float2*)&g_ht[pB * Cch + o0] = vB;
    }
}

// ---------------- K2: conv2 warp-per-pixel on channels-last h --------------
__global__ __launch_bounds__(256) void k_conv2(const float* __restrict__ w1,
                                               const int* __restrict__ check,
                                               float* __restrict__ out) {
    __shared__ float s_w[9 * 6 * 128];     // [t][ch][c]
    const int tid  = threadIdx.x;
    const int lane = tid & 31;
    const int wrp  = tid >> 5;

    for (int e = tid; e < 9 * 6 * 128; e += 256) {
        int c = e & 127, tc = e >> 7;
        int t = tc / 6, ch = tc % 6;
        s_w[e] = w1[ch * Kdim + c * 9 + t];
    }
    __syncthreads();

    const int n  = blockIdx.x * 8 + wrp;
    const int b  = n / NHW, r = n % NHW;
    const int wo = r / Ho, ho = r % Ho;

    float acc[6] = {0,0,0,0,0,0};
    const float* hb = g_ht + ((b * Hh + ho) * Ww + wo) * Cch + lane * 4;
    #pragma unroll
    for (int i = 0; i < 3; i++) {
        #pragma unroll
        for (int j = 0; j < 3; j++) {
            float4 hv = *(const float4*)&hb[(i * Ww + j) * Cch];
            const int t = i * 3 + j;
            #pragma unroll
            for (int ch = 0; ch < 6; ch++) {
                float4 wv = *(const float4*)&s_w[(t * 6 + ch) * 128 + lane * 4];
                acc[ch] += hv.x * wv.x + hv.y * wv.y + hv.z * wv.z + hv.w * wv.w;
            }
        }
    }
    #pragma unroll
    for (int ch = 0; ch < 6; ch++) {
        #pragma unroll
        for (int off = 16; off > 0; off >>= 1)
            acc[ch] += __shfl_xor_sync(0xFFFFFFFFu, acc[ch], off);
    }

    const float scale = 1.0f - (float)check[0];
    const float ident6[6] = {1.f, 0.f, 0.f, 0.f, 1.f, 0.f};
    float th[6];
    #pragma unroll
    for (int ch = 0; ch < 6; ch++) th[ch] = acc[ch] * scale + ident6[ch];

    if (lane < 6) {
        out[OUT_OFF  + ((b * 6 + lane) * Ho + ho) * Ho + wo] = th[lane];
        out[DIFF_OFF + n * 6 + lane] = -(acc[lane] * scale);
    }
    if (lane < 9) {
        int i = lane / 3, j = lane % 3;
        float bi = (2.f * (float)i + 1.f) / 3.f - 1.f;
        float bj = (2.f * (float)j + 1.f) / 3.f - 1.f;
        float gx = th[0] * bj + th[1] * bi + th[2];
        float gy = th[3] * bj + th[4] * bi + th[5];
        out[AUXX_OFF + n * 9 + lane] = (gx + 1.0f + (float)wo) * (2.0f / 55.0f) - 1.0f;
        out[AUXY_OFF + n * 9 + lane] = (gy + 1.0f + (float)ho) * (2.0f / 55.0f) - 1.0f;
    }
}

// ---------------- K3: bilinear gather + tf32 GEMM, tap-streamed ------------
__global__ __launch_bounds__(256) void k_sample(const float* __restrict__ lin_b,
                                                float* __restrict__ out) {
    extern __shared__ float s_buf[];            // [2][32][CH_LD]
    __shared__ int   s_xi[288], s_yi[288];
    __shared__ float s_wx[288], s_wy[288];
    __shared__ int   s_xtoff[32], s_obase[32];

    const int tid  = threadIdx.x;
    const int lane = tid & 31;
    const int wrp  = tid >> 5;
    const int n0   = blockIdx.x * 32;

    if (tid < 32) {
        int n = n0 + tid;
        int b = n / NHW, r = n % NHW, wo = r / Ho, ho = r % Ho;
        s_xtoff[tid] = b * (Hh * Ww * Cch);
        s_obase[tid] = b * (Oo * NHW) + ho * Ho + wo;
    }
    for (int e = tid; e < 288; e += 256) {
        int nn = e / 9, t = e % 9;
        int n = n0 + nn;
        float ax = out[AUXX_OFF + n * 9 + t];
        float ay = out[AUXY_OFF + n * 9 + t];
        float gx = (ax + 1.0f) * 28.0f - 0.5f;
        float gy = (ay + 1.0f) * 28.0f - 0.5f;
        float x0f = floorf(gx), y0f = floorf(gy);
        s_xi[e] = (int)x0f;  s_yi[e] = (int)y0f;
        s_wx[e] = gx - x0f;  s_wy[e] = gy - y0f;
    }
    __syncthreads();

    const int mrow = (wrp & 1) * 16;
    const int nt0  = (wrp >> 1) * 8;
    const int r    = lane >> 2;
    const int q    = lane & 3;

    float acc[8][4];
    #pragma unroll
    for (int i = 0; i < 8; i++)
        #pragma unroll
        for (int j = 0; j < 4; j++) acc[i][j] = 0.f;

    auto gather = [&](int t, float* buf) {
        #pragma unroll
        for (int i = 0; i < 4; i++) {
            const int nn = wrp * 4 + i;
            const int task = nn * 9 + t;
            const int x0 = s_xi[task], y0 = s_yi[task];
            const float wx = s_wx[task], wy = s_wy[task];
            const float w00 = (1.f - wx) * (1.f - wy);
            const float w01 = wx * (1.f - wy);
            const float w10 = (1.f - wx) * wy;
            const float w11 = wx * wy;
            const bool vx0 = (unsigned)x0 < 56u, vx1 = (unsigned)(x0 + 1) < 56u;
            const bool vy0 = (unsigned)y0 < 56u, vy1 = (unsigned)(y0 + 1) < 56u;
            const float* base = g_xt + s_xtoff[nn] + lane * 4;
            const float4 z = make_float4(0.f, 0.f, 0.f, 0.f);
            float4 v00 = (vy0 && vx0) ? *(const float4*)(base + (y0 * Ww + x0) * Cch) : z;
            float4 v01 = (vy0 && vx1) ? *(const float4*)(base + (y0 * Ww + x0 + 1) * Cch) : z;
            float4 v10 = (vy1 && vx0) ? *(const float4*)(base + ((y0 + 1) * Ww + x0) * Cch) : z;
            float4 v11 = (vy1 && vx1) ? *(const float4*)(base + ((y0 + 1) * Ww + x0 + 1) * Cch) : z;
            float4 v;
            v.x = to_tf32(v00.x * w00 + v01.x * w01 + v10.x * w10 + v11.x * w11);
            v.y = to_tf32(v00.y * w00 + v01.y * w01 + v10.y * w10 + v11.y * w11);
            v.z = to_tf32(v00.z * w00 + v01.z * w01 + v10.z * w10 + v11.z * w11);
            v.w = to_tf32(v00.w * w00 + v01.w * w01 + v10.w * w10 + v11.w * w11);
            *(float4*)&buf[nn * CH_LD + lane * 4] = v;
        }
    };

    gather(0, s_buf);
    __syncthreads();

    for (int t = 0; t < 9; t++) {
        float* cur = s_buf + (t & 1) * CH_SZ;
        if (t < 8) gather(t + 1, s_buf + ((t + 1) & 1) * CH_SZ);

        const float* pa  = cur + (mrow + r) * CH_LD + q;
        const float* pa8 = pa + 8 * CH_LD;
        #pragma unroll 4
        for (int ksl = 0; ksl < 16; ksl++) {
            uint32_t a0 = __float_as_uint(pa [ksl * 8]);
            uint32_t a1 = __float_as_uint(pa8[ksl * 8]);
            uint32_t a2 = __float_as_uint(pa [ksl * 8 + 4]);
            uint32_t a3 = __float_as_uint(pa8[ksl * 8 + 4]);
            const float2* wp = g_wpk + (((t * 16 + ksl) * 32) + nt0) * 32 + lane;
            #pragma unroll
            for (int i = 0; i < 8; i++) {
                float2 bv = wp[i * 32];
                MMA(acc[i], a0, a1, a2, a3,
                    __float_as_uint(bv.x), __float_as_uint(bv.y));
            }
        }
        __syncthreads();
    }

    #pragma unroll
    for (int i = 0; i < 8; i++) {
        int o0 = (nt0 + i) * 8 + q * 2;
        float b0 = __ldg(&lin_b[o0]);
        float b1 = __ldg(&lin_b[o0 + 1]);
        int nnA = mrow + r, nnB = nnA + 8;
        out[SCORE_OFF + s_obase[nnA] + o0 * NHW]       = acc[i][0] + b0;
        out[SCORE_OFF + s_obase[nnA] + (o0 + 1) * NHW] = acc[i][1] + b1;
        out[SCORE_OFF + s_obase[nnB] + o0 * NHW]       = acc[i][2] + b0;
        out[SCORE_OFF + s_obase[nnB] + (o0 + 1) * NHW] = acc[i][3] + b1;
    }
}

// ---------------------------------------------------------------------------
extern "C" void kernel_launch(void* const* d_in, const int* in_sizes, int n_in,
                              void* d_out, int out_size) {
    const float* x      = (const float*)d_in[0];
    const float* stn0_w = (const float*)d_in[1];
    const float* stn0_b = (const float*)d_in[2];
    const float* stn1_w = (const float*)d_in[3];
    const float* lin_w  = (const float*)d_in[4];
    const float* lin_b  = (const float*)d_in[5];
    const int*   check  = (const int*)d_in[6];
    float* out = (float*)d_out;

    float2* wpk;  cudaGetSymbolAddress((void**)&wpk,  g_wpk);
    float2* w0pk; cudaGetSymbolAddress((void**)&w0pk, g_w0pk);

    dim3 gxt(Hh, Bsz);
    k_xt<<<gxt, 256>>>(x);

    k_packw<<<(KSTEPS * 32 * 32 + 255) / 256, 256>>>(lin_w, wpk, 32);
    k_packw<<<(KSTEPS * 16 * 32 + 255) / 256, 256>>>(stn0_w, w0pk, 16);

    k_conv1m<<<Npix / 32, 256, SMEM_B>>>(stn0_b);

    k_conv2<<<Ntot / 8, 256>>>(stn1_w, check, out);

    k_sample<<<Ntot / 32, 256, SMEM_B>>>(lin_b, out);
}

// round 11
// speedup vs baseline: 3.6693x; 1.0329x over previous
#include <cuda_runtime.h>
#include <cuda_bf16.h>
#include <cstdint>

// ---------------------------------------------------------------------------
// Conv2d_STN: B=8, C=128, H=W=56, k=3, Ho=Wo=54, N=B*Ho*Wo=23328, O=256
// conv1: implicit-GEMM tf32 mma, 3-stage cp.async tap pipeline.
// sample: bilinear gather + tf32 mma, 2-stage register pipeline.
// ---------------------------------------------------------------------------

#define Bsz   8
#define Cch   128
#define Hh    56
#define Ww    56
#define HW    3136
#define Ho    54
#define NHW   2916
#define Ntot  23328
#define Npix  25088         // 8*56*56
#define Oo    256
#define Kdim  1152
#define KSTEPS 144          // 1152 / 8

#define SCORE_OFF 0
#define DIFF_OFF  5971968
#define OUT_OFF   6111936
#define AUXX_OFF  6251904
#define AUXY_OFF  6461856

#define CH_LD   132                  // tap tile row stride (floats); banks (4r+q) distinct
#define CH_SZ   (32 * CH_LD)         // one tap tile (floats)
#define SMEM_S  (2 * CH_SZ * 4)      // k_sample dynamic smem (33792 B)
#define SMEM_C1 (3 * CH_SZ * 4)      // k_conv1m dynamic smem (50688 B)

__device__ float  g_xt[Bsz * Hh * Ww * Cch];        // x channels-last, tf32-rounded
__device__ float  g_ht[Npix * Cch];                 // conv1 out channels-last
__device__ float2 g_wpk[KSTEPS * 32 * 32];          // lin_w  packed B-frags (tf32)
__device__ float2 g_w0pk[KSTEPS * 16 * 32];         // stn0_w packed B-frags (tf32)

__device__ __forceinline__ float to_tf32(float v) {
    float r;
    asm("cvt.rna.tf32.f32 %0, %1;" : "=f"(r) : "f"(v));
    return r;
}

#define MMA(acc, a0, a1, a2, a3, b0, b1)                                       \
    asm volatile(                                                              \
        "mma.sync.aligned.m16n8k8.row.col.f32.tf32.tf32.f32 "                  \
        "{%0,%1,%2,%3}, {%4,%5,%6,%7}, {%8,%9}, {%0,%1,%2,%3};"                \
        : "+f"(acc[0]), "+f"(acc[1]), "+f"(acc[2]), "+f"(acc[3])               \
        : "r"(a0), "r"(a1), "r"(a2), "r"(a3), "r"(b0), "r"(b1))

// ---------------- K_xt: NCHW -> NHWC transpose of x (+ tf32 round) ---------
__global__ __launch_bounds__(256) void k_xt(const float* __restrict__ x) {
    __shared__ float s[Cch][Ww + 1];
    const int b = blockIdx.y, y = blockIdx.x;
    const int tid = threadIdx.x;
    for (int e = tid; e < Cch * Ww; e += 256) {
        int c = e / Ww, xc = e % Ww;
        s[c][xc] = x[((b * Cch + c) * Hh + y) * Ww + xc];
    }
    __syncthreads();
    for (int e = tid; e < Cch * Ww; e += 256) {
        int xc = e >> 7, c = e & 127;
        g_xt[((b * Hh + y) * Ww + xc) * Cch + c] = to_tf32(s[c][xc]);
    }
}

// ---------------- K_packw: weight -> mma B-fragment layout (tf32) ----------
__global__ void k_packw(const float* __restrict__ w, float2* __restrict__ dst,
                        int ntiles) {
    int idx = blockIdx.x * 256 + threadIdx.x;
    if (idx >= KSTEPS * ntiles * 32) return;
    int lane  = idx & 31;
    int ntile = (idx >> 5) % ntiles;
    int ks    = (idx >> 5) / ntiles;
    int q = lane & 3, n = ntile * 8 + (lane >> 2);
    int kp1 = ks * 8 + q, kp2 = kp1 + 4;
    float v1 = w[n * Kdim + (kp1 & 127) * 9 + (kp1 >> 7)];
    float v2 = w[n * Kdim + (kp2 & 127) * 9 + (kp2 >> 7)];
    dst[idx] = make_float2(to_tf32(v1), to_tf32(v2));
}

// ---------------- K1: conv1 implicit-GEMM, 3-stage cp.async taps -----------
__global__ __launch_bounds__(256) void k_conv1m(const float* __restrict__ bias) {
    extern __shared__ float s_buf[];            // [3][32][CH_LD]
    __shared__ int s_b[32], s_y[32], s_x[32];

    const int tid  = threadIdx.x;
    const int lane = tid & 31;
    const int wrp  = tid >> 5;
    const int p0   = blockIdx.x * 32;

    if (tid < 32) {
        int p = p0 + tid;
        int b = p / HW, rr = p % HW;
        s_b[tid] = b; s_y[tid] = rr / Ww; s_x[tid] = rr % Ww;
    }
    __syncthreads();

    const int mrow = (wrp & 1) * 16;
    const int nt0  = (wrp >> 1) * 4;
    const int r    = lane >> 2;
    const int q    = lane & 3;

    float acc[4][4];
    #pragma unroll
    for (int i = 0; i < 4; i++)
        #pragma unroll
        for (int j = 0; j < 4; j++) acc[i][j] = 0.f;

    // cp.async one tap tile: warp -> 4 pixels, lane -> 4 channels (16B)
    auto issue_tap = [&](int t, float* buf) {
        const int kh = t / 3, kw = t % 3;
        #pragma unroll
        for (int i = 0; i < 4; i++) {
            const int nn = wrp * 4 + i;
            const int yy = s_y[nn] + kh - 1;
            const int xx = s_x[nn] + kw - 1;
            const bool ok = ((unsigned)yy < 56u) && ((unsigned)xx < 56u);
            const int yc = min(max(yy, 0), 55), xc = min(max(xx, 0), 55);
            const float* src =
                &g_xt[(((s_b[nn] * Hh) + yc) * Ww + xc) * Cch + lane * 4];
            uint32_t dst = (uint32_t)__cvta_generic_to_shared(
                &buf[nn * CH_LD + lane * 4]);
            int sz = ok ? 16 : 0;
            asm volatile("cp.async.ca.shared.global [%0], [%1], 16, %2;"
                         :: "r"(dst), "l"(src), "r"(sz));
        }
        asm volatile("cp.async.commit_group;");
    };

    issue_tap(0, s_buf);
    issue_tap(1, s_buf + CH_SZ);

    for (int t = 0; t < 9; t++) {
        if (t == 8) asm volatile("cp.async.wait_group 0;");
        else        asm volatile("cp.async.wait_group 1;");
        __syncthreads();
        if (t < 7) issue_tap(t + 2, s_buf + ((t + 2) % 3) * CH_SZ);

        const float* cur = s_buf + (t % 3) * CH_SZ;
        const float* pa  = cur + (mrow + r) * CH_LD + q;
        const float* pa8 = pa + 8 * CH_LD;
        #pragma unroll 4
        for (int ksl = 0; ksl < 16; ksl++) {
            uint32_t a0 = __float_as_uint(pa [ksl * 8]);
            uint32_t a1 = __float_as_uint(pa8[ksl * 8]);
            uint32_t a2 = __float_as_uint(pa [ksl * 8 + 4]);
            uint32_t a3 = __float_as_uint(pa8[ksl * 8 + 4]);
            const float2* wp = g_w0pk + (((t * 16 + ksl) * 16) + nt0) * 32 + lane;
            #pragma unroll
            for (int i = 0; i < 4; i++) {
                float2 bv = wp[i * 32];
                MMA(acc[i], a0, a1, a2, a3,
                    __float_as_uint(bv.x), __float_as_uint(bv.y));
            }
        }
        __syncthreads();
    }

    #pragma unroll
    for (int i = 0; i < 4; i++) {
        int o0 = (nt0 + i) * 8 + q * 2;
        float b0 = __ldg(&bias[o0]);
        float b1 = __ldg(&bias[o0 + 1]);
        int pA = p0 + mrow + r, pB = pA + 8;
        float2 vA = make_float2(fmaxf(acc[i][0] + b0, 0.f), fmaxf(acc[i][1] + b1, 0.f));
        float2 vB = make_float2(fmaxf(acc[i][2] + b0, 0.f), fmaxf(acc[i][3] + b1, 0.f));
        *(float2*)&g_ht[pA * Cch + o0] = vA;
        *(float2*)&g_ht[pB * Cch + o0] = vB;
    }
}

// ---------------- K2: conv2 warp-per-pixel on channels-last h --------------
__global__ __launch_bounds__(256) void k_conv2(const float* __restrict__ w1,
                                               const int* __restrict__ check,
                                               float* __restrict__ out) {
    __shared__ float s_w[9 * 6 * 128];     // [t][ch][c]
    const int tid  = threadIdx.x;
    const int lane = tid & 31;
    const int wrp  = tid >> 5;

    for (int e = tid; e < 9 * 6 * 128; e += 256) {
        int c = e & 127, tc = e >> 7;
        int t = tc / 6, ch = tc % 6;
        s_w[e] = w1[ch * Kdim + c * 9 + t];
    }
    __syncthreads();

    const int n  = blockIdx.x * 8 + wrp;
    const int b  = n / NHW, r = n % NHW;
    const int wo = r / Ho, ho = r % Ho;

    float acc[6] = {0,0,0,0,0,0};
    const float* hb = g_ht + ((b * Hh + ho) * Ww + wo) * Cch + lane * 4;
    #pragma unroll
    for (int i = 0; i < 3; i++) {
        #pragma unroll
        for (int j = 0; j < 3; j++) {
            float4 hv = *(const float4*)&hb[(i * Ww + j) * Cch];
            const int t = i * 3 + j;
            #pragma unroll
            for (int ch = 0; ch < 6; ch++) {
                float4 wv = *(const float4*)&s_w[(t * 6 + ch) * 128 + lane * 4];
                acc[ch] += hv.x * wv.x + hv.y * wv.y + hv.z * wv.z + hv.w * wv.w;
            }
        }
    }
    #pragma unroll
    for (int ch = 0; ch < 6; ch++) {
        #pragma unroll
        for (int off = 16; off > 0; off >>= 1)
            acc[ch] += __shfl_xor_sync(0xFFFFFFFFu, acc[ch], off);
    }

    const float scale = 1.0f - (float)check[0];
    const float ident6[6] = {1.f, 0.f, 0.f, 0.f, 1.f, 0.f};
    float th[6];
    #pragma unroll
    for (int ch = 0; ch < 6; ch++) th[ch] = acc[ch] * scale + ident6[ch];

    if (lane < 6) {
        out[OUT_OFF  + ((b * 6 + lane) * Ho + ho) * Ho + wo] = th[lane];
        out[DIFF_OFF + n * 6 + lane] = -(acc[lane] * scale);
    }
    if (lane < 9) {
        int i = lane / 3, j = lane % 3;
        float bi = (2.f * (float)i + 1.f) / 3.f - 1.f;
        float bj = (2.f * (float)j + 1.f) / 3.f - 1.f;
        float gx = th[0] * bj + th[1] * bi + th[2];
        float gy = th[3] * bj + th[4] * bi + th[5];
        out[AUXX_OFF + n * 9 + lane] = (gx + 1.0f + (float)wo) * (2.0f / 55.0f) - 1.0f;
        out[AUXY_OFF + n * 9 + lane] = (gy + 1.0f + (float)ho) * (2.0f / 55.0f) - 1.0f;
    }
}

// ---------------- K3: bilinear gather + tf32 GEMM, tap-streamed ------------
__global__ __launch_bounds__(256) void k_sample(const float* __restrict__ lin_b,
                                                float* __restrict__ out) {
    extern __shared__ float s_buf[];            // [2][32][CH_LD]
    __shared__ int   s_xi[288], s_yi[288];
    __shared__ float s_wx[288], s_wy[288];
    __shared__ int   s_xtoff[32], s_obase[32];

    const int tid  = threadIdx.x;
    const int lane = tid & 31;
    const int wrp  = tid >> 5;
    const int n0   = blockIdx.x * 32;

    if (tid < 32) {
        int n = n0 + tid;
        int b = n / NHW, r = n % NHW, wo = r / Ho, ho = r % Ho;
        s_xtoff[tid] = b * (Hh * Ww * Cch);
        s_obase[tid] = b * (Oo * NHW) + ho * Ho + wo;
    }
    for (int e = tid; e < 288; e += 256) {
        int nn = e / 9, t = e % 9;
        int n = n0 + nn;
        float ax = out[AUXX_OFF + n * 9 + t];
        float ay = out[AUXY_OFF + n * 9 + t];
        float gx = (ax + 1.0f) * 28.0f - 0.5f;
        float gy = (ay + 1.0f) * 28.0f - 0.5f;
        float x0f = floorf(gx), y0f = floorf(gy);
        s_xi[e] = (int)x0f;  s_yi[e] = (int)y0f;
        s_wx[e] = gx - x0f;  s_wy[e] = gy - y0f;
    }
    __syncthreads();

    const int mrow = (wrp & 1) * 16;
    const int nt0  = (wrp >> 1) * 8;
    const int r    = lane >> 2;
    const int q    = lane & 3;

    float acc[8][4];
    #pragma unroll
    for (int i = 0; i < 8; i++)
        #pragma unroll
        for (int j = 0; j < 4; j++) acc[i][j] = 0.f;

    auto gather = [&](int t, float* buf) {
        #pragma unroll
        for (int i = 0; i < 4; i++) {
            const int nn = wrp * 4 + i;
            const int task = nn * 9 + t;
            const int x0 = s_xi[task], y0 = s_yi[task];
            const float wx = s_wx[task], wy = s_wy[task];
            const float w00 = (1.f - wx) * (1.f - wy);
            const float w01 = wx * (1.f - wy);
            const float w10 = (1.f - wx) * wy;
            const float w11 = wx * wy;
            const bool vx0 = (unsigned)x0 < 56u, vx1 = (unsigned)(x0 + 1) < 56u;
            const bool vy0 = (unsigned)y0 < 56u, vy1 = (unsigned)(y0 + 1) < 56u;
            const float* base = g_xt + s_xtoff[nn] + lane * 4;
            const float4 z = make_float4(0.f, 0.f, 0.f, 0.f);
            float4 v00 = (vy0 && vx0) ? *(const float4*)(base + (y0 * Ww + x0) * Cch) : z;
            float4 v01 = (vy0 && vx1) ? *(const float4*)(base + (y0 * Ww + x0 + 1) * Cch) : z;
            float4 v10 = (vy1 && vx0) ? *(const float4*)(base + ((y0 + 1) * Ww + x0) * Cch) : z;
            float4 v11 = (vy1 && vx1) ? *(const float4*)(base + ((y0 + 1) * Ww + x0 + 1) * Cch) : z;
            float4 v;
            v.x = to_tf32(v00.x * w00 + v01.x * w01 + v10.x * w10 + v11.x * w11);
            v.y = to_tf32(v00.y * w00 + v01.y * w01 + v10.y * w10 + v11.y * w11);
            v.z = to_tf32(v00.z * w00 + v01.z * w01 + v10.z * w10 + v11.z * w11);
            v.w = to_tf32(v00.w * w00 + v01.w * w01 + v10.w * w10 + v11.w * w11);
            *(float4*)&buf[nn * CH_LD + lane * 4] = v;
        }
    };

    gather(0, s_buf);
    __syncthreads();

    for (int t = 0; t < 9; t++) {
        float* cur = s_buf + (t & 1) * CH_SZ;
        if (t < 8) gather(t + 1, s_buf + ((t + 1) & 1) * CH_SZ);

        const float* pa  = cur + (mrow + r) * CH_LD + q;
        const float* pa8 = pa + 8 * CH_LD;
        #pragma unroll 4
        for (int ksl = 0; ksl < 16; ksl++) {
            uint32_t a0 = __float_as_uint(pa [ksl * 8]);
            uint32_t a1 = __float_as_uint(pa8[ksl * 8]);
            uint32_t a2 = __float_as_uint(pa [ksl * 8 + 4]);
            uint32_t a3 = __float_as_uint(pa8[ksl * 8 + 4]);
            const float2* wp = g_wpk + (((t * 16 + ksl) * 32) + nt0) * 32 + lane;
            #pragma unroll
            for (int i = 0; i < 8; i++) {
                float2 bv = wp[i * 32];
                MMA(acc[i], a0, a1, a2, a3,
                    __float_as_uint(bv.x), __float_as_uint(bv.y));
            }
        }
        __syncthreads();
    }

    #pragma unroll
    for (int i = 0; i < 8; i++) {
        int o0 = (nt0 + i) * 8 + q * 2;
        float b0 = __ldg(&lin_b[o0]);
        float b1 = __ldg(&lin_b[o0 + 1]);
        int nnA = mrow + r, nnB = nnA + 8;
        out[SCORE_OFF + s_obase[nnA] + o0 * NHW]       = acc[i][0] + b0;
        out[SCORE_OFF + s_obase[nnA] + (o0 + 1) * NHW] = acc[i][1] + b1;
        out[SCORE_OFF + s_obase[nnB] + o0 * NHW]       = acc[i][2] + b0;
        out[SCORE_OFF + s_obase[nnB] + (o0 + 1) * NHW] = acc[i][3] + b1;
    }
}

// ---------------------------------------------------------------------------
extern "C" void kernel_launch(void* const* d_in, const int* in_sizes, int n_in,
                              void* d_out, int out_size) {
    const float* x      = (const float*)d_in[0];
    const float* stn0_w = (const float*)d_in[1];
    const float* stn0_b = (const float*)d_in[2];
    const float* stn1_w = (const float*)d_in[3];
    const float* lin_w  = (const float*)d_in[4];
    const float* lin_b  = (const float*)d_in[5];
    const int*   check  = (const int*)d_in[6];
    float* out = (float*)d_out;

    cudaFuncSetAttribute(k_conv1m, cudaFuncAttributeMaxDynamicSharedMemorySize,
                         SMEM_C1);

    float2* wpk;  cudaGetSymbolAddress((void**)&wpk,  g_wpk);
    float2* w0pk; cudaGetSymbolAddress((void**)&w0pk, g_w0pk);

    dim3 gxt(Hh, Bsz);
    k_xt<<<gxt, 256>>>(x);

    k_packw<<<(KSTEPS * 32 * 32 + 255) / 256, 256>>>(lin_w, wpk, 32);
    k_packw<<<(KSTEPS * 16 * 32 + 255) / 256, 256>>>(stn0_w, w0pk, 16);

    k_conv1m<<<Npix / 32, 256, SMEM_C1>>>(stn0_b);

    k_conv2<<<Ntot / 8, 256>>>(stn1_w, check, out);

    k_sample<<<Ntot / 32, 256, SMEM_S>>>(lin_b, out);
}

// round 15
// speedup vs baseline: 4.6479x; 1.2667x over previous
#include <cuda_runtime.h>
#include <cuda_bf16.h>
#include <cstdint>

// ---------------------------------------------------------------------------
// Conv2d_STN: B=8, C=128, H=W=56, k=3, Ho=Wo=54, N=B*Ho*Wo=23328, O=256
// conv1: implicit-GEMM tf32 mma, 64-px blocks, m16xn64 warp tiles (k_sample clone)
// sample: bilinear gather + tf32 mma, 2-stage register pipeline.
// ---------------------------------------------------------------------------

#define Bsz   8
#define Cch   128
#define Hh    56
#define Ww    56
#define HW    3136
#define Ho    54
#define NHW   2916
#define Ntot  23328
#define Npix  25088         // 8*56*56
#define Oo    256
#define Kdim  1152
#define KSTEPS 144          // 1152 / 8

#define SCORE_OFF 0
#define DIFF_OFF  5971968
#define OUT_OFF   6111936
#define AUXX_OFF  6251904
#define AUXY_OFF  6461856

#define CH_LD   132                  // tile row stride (floats); banks (4r+q) distinct
#define CH_SZ   (32 * CH_LD)         // sample tap tile (32 rows)
#define C1_SZ   (64 * CH_LD)         // conv1 tap tile (64 rows)
#define SMEM_S  (2 * CH_SZ * 4)      // k_sample dynamic smem (33792 B)
#define SMEM_C1 (2 * C1_SZ * 4)     // k_conv1m dynamic smem (67584 B)

__device__ float  g_xt[Bsz * Hh * Ww * Cch];        // x channels-last, tf32-rounded
__device__ float  g_ht[Npix * Cch];                 // conv1 out channels-last
__device__ float2 g_wpk[KSTEPS * 32 * 32];          // lin_w  packed B-frags (tf32)
__device__ float2 g_w0pk[KSTEPS * 16 * 32];         // stn0_w packed B-frags (tf32)

__device__ __forceinline__ float to_tf32(float v) {
    float r;
    asm("cvt.rna.tf32.f32 %0, %1;" : "=f"(r) : "f"(v));
    return r;
}

#define MMA(acc, a0, a1, a2, a3, b0, b1)                                       \
    asm volatile(                                                              \
        "mma.sync.aligned.m16n8k8.row.col.f32.tf32.tf32.f32 "                  \
        "{%0,%1,%2,%3}, {%4,%5,%6,%7}, {%8,%9}, {%0,%1,%2,%3};"                \
        : "+f"(acc[0]), "+f"(acc[1]), "+f"(acc[2]), "+f"(acc[3])               \
        : "r"(a0), "r"(a1), "r"(a2), "r"(a3), "r"(b0), "r"(b1))

// ---------------- K_xt: NCHW -> NHWC transpose of x (+ tf32 round) ---------
__global__ __launch_bounds__(256) void k_xt(const float* __restrict__ x) {
    __shared__ float s[Cch][Ww + 1];
    const int b = blockIdx.y, y = blockIdx.x;
    const int tid = threadIdx.x;
    for (int e = tid; e < Cch * Ww; e += 256) {
        int c = e / Ww, xc = e % Ww;
        s[c][xc] = x[((b * Cch + c) * Hh + y) * Ww + xc];
    }
    __syncthreads();
    for (int e = tid; e < Cch * Ww; e += 256) {
        int xc = e >> 7, c = e & 127;
        g_xt[((b * Hh + y) * Ww + xc) * Cch + c] = to_tf32(s[c][xc]);
    }
}

// ---------------- K_packw: weight -> mma B-fragment layout (tf32) ----------
__global__ void k_packw(const float* __restrict__ w, float2* __restrict__ dst,
                        int ntiles) {
    int idx = blockIdx.x * 256 + threadIdx.x;
    if (idx >= KSTEPS * ntiles * 32) return;
    int lane  = idx & 31;
    int ntile = (idx >> 5) % ntiles;
    int ks    = (idx >> 5) / ntiles;
    int q = lane & 3, n = ntile * 8 + (lane >> 2);
    int kp1 = ks * 8 + q, kp2 = kp1 + 4;
    float v1 = w[n * Kdim + (kp1 & 127) * 9 + (kp1 >> 7)];
    float v2 = w[n * Kdim + (kp2 & 127) * 9 + (kp2 >> 7)];
    dst[idx] = make_float2(to_tf32(v1), to_tf32(v2));
}

// ---------------- K1: conv1 implicit-GEMM, 64 px, m16xn64 warps ------------
__global__ __launch_bounds__(256) void k_conv1m(const float* __restrict__ bias) {
    extern __shared__ float s_buf[];            // [2][64][CH_LD]
    __shared__ int s_b[64], s_y[64], s_x[64];

    const int tid  = threadIdx.x;
    const int lane = tid & 31;
    const int wrp  = tid >> 5;
    const int p0   = blockIdx.x * 64;

    if (tid < 64) {
        int p = p0 + tid;
        int b = p / HW, rr = p % HW;
        s_b[tid] = b; s_y[tid] = rr / Ww; s_x[tid] = rr % Ww;
    }
    __syncthreads();

    const int mrow = (wrp & 3) * 16;      // 4 m-slabs over 64 px
    const int nt0  = (wrp >> 2) * 8;      // 2 n-groups x 8 tiles = 16 tiles (N=128)
    const int r    = lane >> 2;
    const int q    = lane & 3;

    float acc[8][4];
    #pragma unroll
    for (int i = 0; i < 8; i++)
        #pragma unroll
        for (int j = 0; j < 4; j++) acc[i][j] = 0.f;

    // gather tap t: warp -> 8 pixels, lane -> 4 channels (16B, zero-pad)
    auto gather = [&](int t, float* buf) {
        const int kh = t / 3, kw = t % 3;
        #pragma unroll
        for (int i = 0; i < 8; i++) {
            const int nn = wrp * 8 + i;
            const int yy = s_y[nn] + kh - 1;
            const int xx = s_x[nn] + kw - 1;
            float4 v = make_float4(0.f, 0.f, 0.f, 0.f);
            if ((unsigned)yy < 56u && (unsigned)xx < 56u)
                v = *(const float4*)&g_xt[(((s_b[nn] * Hh) + yy) * Ww + xx) * Cch + lane * 4];
            *(float4*)&buf[nn * CH_LD + lane * 4] = v;
        }
    };

    gather(0, s_buf);
    __syncthreads();

    for (int t = 0; t < 9; t++) {
        float* cur = s_buf + (t & 1) * C1_SZ;
        if (t < 8) gather(t + 1, s_buf + ((t + 1) & 1) * C1_SZ);

        const float* pa  = cur + (mrow + r) * CH_LD + q;
        const float* pa8 = pa + 8 * CH_LD;
        #pragma unroll 4
        for (int ksl = 0; ksl < 16; ksl++) {
            uint32_t a0 = __float_as_uint(pa [ksl * 8]);
            uint32_t a1 = __float_as_uint(pa8[ksl * 8]);
            uint32_t a2 = __float_as_uint(pa [ksl * 8 + 4]);
            uint32_t a3 = __float_as_uint(pa8[ksl * 8 + 4]);
            const float2* wp = g_w0pk + (((t * 16 + ksl) * 16) + nt0) * 32 + lane;
            #pragma unroll
            for (int i = 0; i < 8; i++) {
                float2 bv = wp[i * 32];
                MMA(acc[i], a0, a1, a2, a3,
                    __float_as_uint(bv.x), __float_as_uint(bv.y));
            }
        }
        __syncthreads();
    }

    #pragma unroll
    for (int i = 0; i < 8; i++) {
        int o0 = (nt0 + i) * 8 + q * 2;
        float b0 = __ldg(&bias[o0]);
        float b1 = __ldg(&bias[o0 + 1]);
        int pA = p0 + mrow + r, pB = pA + 8;
        float2 vA = make_float2(fmaxf(acc[i][0] + b0, 0.f), fmaxf(acc[i][1] + b1, 0.f));
        float2 vB = make_float2(fmaxf(acc[i][2] + b0, 0.f), fmaxf(acc[i][3] + b1, 0.f));
        *(float2*)&g_ht[pA * Cch + o0] = vA;
        *(float2*)&g_ht[pB * Cch + o0] = vB;
    }
}

// ---------------- K2: conv2 warp-per-pixel on channels-last h --------------
__global__ __launch_bounds__(256) void k_conv2(const float* __restrict__ w1,
                                               const int* __restrict__ check,
                                               float* __restrict__ out) {
    __shared__ float s_w[9 * 6 * 128];     // [t][ch][c]
    const int tid  = threadIdx.x;
    const int lane = tid & 31;
    const int wrp  = tid >> 5;

    for (int e = tid; e < 9 * 6 * 128; e += 256) {
        int c = e & 127, tc = e >> 7;
        int t = tc / 6, ch = tc % 6;
        s_w[e] = w1[ch * Kdim + c * 9 + t];
    }
    __syncthreads();

    const int n  = blockIdx.x * 8 + wrp;
    const int b  = n / NHW, r = n % NHW;
    const int wo = r / Ho, ho = r % Ho;

    float acc[6] = {0,0,0,0,0,0};
    const float* hb = g_ht + ((b * Hh + ho) * Ww + wo) * Cch + lane * 4;
    #pragma unroll
    for (int i = 0; i < 3; i++) {
        #pragma unroll
        for (int j = 0; j < 3; j++) {
            float4 hv = *(const float4*)&hb[(i * Ww + j) * Cch];
            const int t = i * 3 + j;
            #pragma unroll
            for (int ch = 0; ch < 6; ch++) {
                float4 wv = *(const float4*)&s_w[(t * 6 + ch) * 128 + lane * 4];
                acc[ch] += hv.x * wv.x + hv.y * wv.y + hv.z * wv.z + hv.w * wv.w;
            }
        }
    }
    #pragma unroll
    for (int ch = 0; ch < 6; ch++) {
        #pragma unroll
        for (int off = 16; off > 0; off >>= 1)
            acc[ch] += __shfl_xor_sync(0xFFFFFFFFu, acc[ch], off);
    }

    const float scale = 1.0f - (float)check[0];
    const float ident6[6] = {1.f, 0.f, 0.f, 0.f, 1.f, 0.f};
    float th[6];
    #pragma unroll
    for (int ch = 0; ch < 6; ch++) th[ch] = acc[ch] * scale + ident6[ch];

    if (lane < 6) {
        out[OUT_OFF  + ((b * 6 + lane) * Ho + ho) * Ho + wo] = th[lane];
        out[DIFF_OFF + n * 6 + lane] = -(acc[lane] * scale);
    }
    if (lane < 9) {
        int i = lane / 3, j = lane % 3;
        float bi = (2.f * (float)i + 1.f) / 3.f - 1.f;
        float bj = (2.f * (float)j + 1.f) / 3.f - 1.f;
        float gx = th[0] * bj + th[1] * bi + th[2];
        float gy = th[3] * bj + th[4] * bi + th[5];
        out[AUXX_OFF + n * 9 + lane] = (gx + 1.0f + (float)wo) * (2.0f / 55.0f) - 1.0f;
        out[AUXY_OFF + n * 9 + lane] = (gy + 1.0f + (float)ho) * (2.0f / 55.0f) - 1.0f;
    }
}

// ---------------- K3: bilinear gather + tf32 GEMM, tap-streamed ------------
__global__ __launch_bounds__(256) void k_sample(const float* __restrict__ lin_b,
                                                float* __restrict__ out) {
    extern __shared__ float s_buf[];            // [2][32][CH_LD]
    __shared__ int   s_xi[288], s_yi[288];
    __shared__ float s_wx[288], s_wy[288];
    __shared__ int   s_xtoff[32], s_obase[32];

    const int tid  = threadIdx.x;
    const int lane = tid & 31;
    const int wrp  = tid >> 5;
    const int n0   = blockIdx.x * 32;

    if (tid < 32) {
        int n = n0 + tid;
        int b = n / NHW, r = n % NHW, wo = r / Ho, ho = r % Ho;
        s_xtoff[tid] = b * (Hh * Ww * Cch);
        s_obase[tid] = b * (Oo * NHW) + ho * Ho + wo;
    }
    for (int e = tid; e < 288; e += 256) {
        int nn = e / 9, t = e % 9;
        int n = n0 + nn;
        float ax = out[AUXX_OFF + n * 9 + t];
        float ay = out[AUXY_OFF + n * 9 + t];
        float gx = (ax + 1.0f) * 28.0f - 0.5f;
        float gy = (ay + 1.0f) * 28.0f - 0.5f;
        float x0f = floorf(gx), y0f = floorf(gy);
        s_xi[e] = (int)x0f;  s_yi[e] = (int)y0f;
        s_wx[e] = gx - x0f;  s_wy[e] = gy - y0f;
    }
    __syncthreads();

    const int mrow = (wrp & 1) * 16;
    const int nt0  = (wrp >> 1) * 8;
    const int r    = lane >> 2;
    const int q    = lane & 3;

    float acc[8][4];
    #pragma unroll
    for (int i = 0; i < 8; i++)
        #pragma unroll
        for (int j = 0; j < 4; j++) acc[i][j] = 0.f;

    auto gather = [&](int t, float* buf) {
        #pragma unroll
        for (int i = 0; i < 4; i++) {
            const int nn = wrp * 4 + i;
            const int task = nn * 9 + t;
            const int x0 = s_xi[task], y0 = s_yi[task];
            const float wx = s_wx[task], wy = s_wy[task];
            const float w00 = (1.f - wx) * (1.f - wy);
            const float w01 = wx * (1.f - wy);
            const float w10 = (1.f - wx) * wy;
            const float w11 = wx * wy;
            const bool vx0 = (unsigned)x0 < 56u, vx1 = (unsigned)(x0 + 1) < 56u;
            const bool vy0 = (unsigned)y0 < 56u, vy1 = (unsigned)(y0 + 1) < 56u;
            const float* base = g_xt + s_xtoff[nn] + lane * 4;
            const float4 z = make_float4(0.f, 0.f, 0.f, 0.f);
            float4 v00 = (vy0 && vx0) ? *(const float4*)(base + (y0 * Ww + x0) * Cch) : z;
            float4 v01 = (vy0 && vx1) ? *(const float4*)(base + (y0 * Ww + x0 + 1) * Cch) : z;
            float4 v10 = (vy1 && vx0) ? *(const float4*)(base + ((y0 + 1) * Ww + x0) * Cch) : z;
            float4 v11 = (vy1 && vx1) ? *(const float4*)(base + ((y0 + 1) * Ww + x0 + 1) * Cch) : z;
            float4 v;
            v.x = to_tf32(v00.x * w00 + v01.x * w01 + v10.x * w10 + v11.x * w11);
            v.y = to_tf32(v00.y * w00 + v01.y * w01 + v10.y * w10 + v11.y * w11);
            v.z = to_tf32(v00.z * w00 + v01.z * w01 + v10.z * w10 + v11.z * w11);
            v.w = to_tf32(v00.w * w00 + v01.w * w01 + v10.w * w10 + v11.w * w11);
            *(float4*)&buf[nn * CH_LD + lane * 4] = v;
        }
    };

    gather(0, s_buf);
    __syncthreads();

    for (int t = 0; t < 9; t++) {
        float* cur = s_buf + (t & 1) * CH_SZ;
        if (t < 8) gather(t + 1, s_buf + ((t + 1) & 1) * CH_SZ);

        const float* pa  = cur + (mrow + r) * CH_LD + q;
        const float* pa8 = pa + 8 * CH_LD;
        #pragma unroll 4
        for (int ksl = 0; ksl < 16; ksl++) {
            uint32_t a0 = __float_as_uint(pa [ksl * 8]);
            uint32_t a1 = __float_as_uint(pa8[ksl * 8]);
            uint32_t a2 = __float_as_uint(pa [ksl * 8 + 4]);
            uint32_t a3 = __float_as_uint(pa8[ksl * 8 + 4]);
            const float2* wp = g_wpk + (((t * 16 + ksl) * 32) + nt0) * 32 + lane;
            #pragma unroll
            for (int i = 0; i < 8; i++) {
                float2 bv = wp[i * 32];
                MMA(acc[i], a0, a1, a2, a3,
                    __float_as_uint(bv.x), __float_as_uint(bv.y));
            }
        }
        __syncthreads();
    }

    #pragma unroll
    for (int i = 0; i < 8; i++) {
        int o0 = (nt0 + i) * 8 + q * 2;
        float b0 = __ldg(&lin_b[o0]);
        float b1 = __ldg(&lin_b[o0 + 1]);
        int nnA = mrow + r, nnB = nnA + 8;
        out[SCORE_OFF + s_obase[nnA] + o0 * NHW]       = acc[i][0] + b0;
        out[SCORE_OFF + s_obase[nnA] + (o0 + 1) * NHW] = acc[i][1] + b1;
        out[SCORE_OFF + s_obase[nnB] + o0 * NHW]       = acc[i][2] + b0;
        out[SCORE_OFF + s_obase[nnB] + (o0 + 1) * NHW] = acc[i][3] + b1;
    }
}

// ---------------------------------------------------------------------------
extern "C" void kernel_launch(void* const* d_in, const int* in_sizes, int n_in,
                              void* d_out, int out_size) {
    const float* x      = (const float*)d_in[0];
    const float* stn0_w = (const float*)d_in[1];
    const float* stn0_b = (const float*)d_in[2];
    const float* stn1_w = (const float*)d_in[3];
    const float* lin_w  = (const float*)d_in[4];
    const float* lin_b  = (const float*)d_in[5];
    const int*   check  = (const int*)d_in[6];
    float* out = (float*)d_out;

    cudaFuncSetAttribute(k_conv1m, cudaFuncAttributeMaxDynamicSharedMemorySize,
                         SMEM_C1);

    float2* wpk;  cudaGetSymbolAddress((void**)&wpk,  g_wpk);
    float2* w0pk; cudaGetSymbolAddress((void**)&w0pk, g_w0pk);

    dim3 gxt(Hh, Bsz);
    k_xt<<<gxt, 256>>>(x);

    k_packw<<<(KSTEPS * 32 * 32 + 255) / 256, 256>>>(lin_w, wpk, 32);
    k_packw<<<(KSTEPS * 16 * 32 + 255) / 256, 256>>>(stn0_w, w0pk, 16);

    k_conv1m<<<Npix / 64, 256, SMEM_C1>>>(stn0_b);

    k_conv2<<<Ntot / 8, 256>>>(stn1_w, check, out);

    k_sample<<<Ntot / 32, 256, SMEM_S>>>(lin_b, out);
}